// round 12
// baseline (speedup 1.0000x reference)
#include <cuda_runtime.h>
#include <cuda_fp16.h>
#include <math.h>
#include <stdint.h>

#define Bsz  2
#define Tseq 1024
#define Emb  2048
#define NH   16
#define NG   4
#define HSZ  128
#define NL   4
#define Voc  32000
#define FFD  8192
#define NTOK (Bsz*Tseq)                 // 2048
#define QKVD ((NH+2*NG)*HSZ)            // 3072
#define EPSF 1e-5f
#define ASCALE 0.08838834764831845f     // 1/sqrt(128)

// ---------------- scratch (device globals; no allocation allowed) ----------
__device__ __align__(128) float g_x  [NTOK*Emb];
__device__ __align__(128) float g_qkv[NTOK*QKVD];
__device__ __align__(128) float g_s  [(size_t)Bsz*NH*Tseq*Tseq];

// activation fp16 planes (hi/lo split)
__device__ __align__(128) __half g_a_hi[NTOK*Emb];
__device__ __align__(128) __half g_a_lo[NTOK*Emb];
__device__ __align__(128) __half g_h_hi[NTOK*FFD];
__device__ __align__(128) __half g_h_lo[NTOK*FFD];

// attention fp16 planes
__device__ __align__(128) __half g_q_hi[(size_t)Bsz*NH*Tseq*HSZ];
__device__ __align__(128) __half g_q_lo[(size_t)Bsz*NH*Tseq*HSZ];
__device__ __align__(128) __half g_k_hi[(size_t)Bsz*NG*Tseq*HSZ];
__device__ __align__(128) __half g_k_lo[(size_t)Bsz*NG*Tseq*HSZ];
__device__ __align__(128) __half g_vt_hi[(size_t)Bsz*NG*HSZ*Tseq];
__device__ __align__(128) __half g_vt_lo[(size_t)Bsz*NG*HSZ*Tseq];
__device__ __align__(128) __half g_p_hi[(size_t)Bsz*NH*Tseq*Tseq];
__device__ __align__(128) __half g_p_lo[(size_t)Bsz*NH*Tseq*Tseq];

// weight fp16 planes (converted once per launch)
__device__ __align__(128) __half g_wqkv_h[(size_t)NL*QKVD*Emb];
__device__ __align__(128) __half g_wattn_h[(size_t)NL*Emb*(NH*HSZ)];
__device__ __align__(128) __half g_wfc_h [(size_t)NL*FFD*Emb];
__device__ __align__(128) __half g_wmlp_h[(size_t)NL*Emb*FFD];
__device__ __align__(128) __half g_wlm_h [(size_t)Voc*Emb];

// ==================== helpers ====================
__device__ __forceinline__ uint32_t smem_u32(const void* p) {
    uint32_t a;
    asm("{ .reg .u64 t; cvta.to.shared.u64 t, %1; cvt.u32.u64 %0, t; }" : "=r"(a) : "l"(p));
    return a;
}
__device__ __forceinline__ void ldsm_x4(uint32_t* r, uint32_t addr) {
    asm volatile("ldmatrix.sync.aligned.m8n8.x4.shared.b16 {%0,%1,%2,%3}, [%4];"
        : "=r"(r[0]), "=r"(r[1]), "=r"(r[2]), "=r"(r[3]) : "r"(addr));
}
__device__ __forceinline__ void ldsm_x2(uint32_t* r, uint32_t addr) {
    asm volatile("ldmatrix.sync.aligned.m8n8.x2.shared.b16 {%0,%1}, [%2];"
        : "=r"(r[0]), "=r"(r[1]) : "r"(addr));
}
__device__ __forceinline__ void mma_f16(float* d, const uint32_t* a, const uint32_t* b) {
    asm volatile(
        "mma.sync.aligned.m16n8k16.row.col.f32.f16.f16.f32 "
        "{%0,%1,%2,%3}, {%4,%5,%6,%7}, {%8,%9}, {%0,%1,%2,%3};"
        : "+f"(d[0]), "+f"(d[1]), "+f"(d[2]), "+f"(d[3])
        : "r"(a[0]), "r"(a[1]), "r"(a[2]), "r"(a[3]), "r"(b[0]), "r"(b[1]));
}
__device__ __forceinline__ void cp16(uint32_t saddr, const void* gptr) {
    asm volatile("cp.async.cg.shared.global [%0], [%1], 16;" :: "r"(saddr), "l"(gptr));
}
#define CP_COMMIT() asm volatile("cp.async.commit_group;" ::: "memory")
#define CP_WAIT(n)  asm volatile("cp.async.wait_group %0;" :: "n"(n) : "memory")

__device__ __forceinline__ float gelu_f(float x) {
    return 0.5f*x*(1.0f + tanhf(0.7978845608028654f*(x + 0.044715f*x*x*x)));
}
__device__ __forceinline__ void split4(float4 v, uint2& hh, uint2& ll) {
    __half h0 = __float2half_rn(v.x);
    __half h1 = __float2half_rn(v.y);
    __half h2 = __float2half_rn(v.z);
    __half h3 = __float2half_rn(v.w);
    __half l0 = __float2half_rn(v.x - __half2float(h0));
    __half l1 = __float2half_rn(v.y - __half2float(h1));
    __half l2 = __float2half_rn(v.z - __half2float(h2));
    __half l3 = __float2half_rn(v.w - __half2float(h3));
    hh.x = ((uint32_t)__half_as_ushort(h1) << 16) | __half_as_ushort(h0);
    hh.y = ((uint32_t)__half_as_ushort(h3) << 16) | __half_as_ushort(h2);
    ll.x = ((uint32_t)__half_as_ushort(l1) << 16) | __half_as_ushort(l0);
    ll.y = ((uint32_t)__half_as_ushort(l3) << 16) | __half_as_ushort(l2);
}
__device__ __forceinline__ void split2(float2 v, uint32_t& hh, uint32_t& ll) {
    __half h0 = __float2half_rn(v.x);
    __half h1 = __float2half_rn(v.y);
    __half l0 = __float2half_rn(v.x - __half2float(h0));
    __half l1 = __float2half_rn(v.y - __half2float(h1));
    hh = ((uint32_t)__half_as_ushort(h1) << 16) | __half_as_ushort(h0);
    ll = ((uint32_t)__half_as_ushort(l1) << 16) | __half_as_ushort(l0);
}

// ---------------- weight fp32 -> fp16 convert ----------------
__global__ void __launch_bounds__(256) wconv_kernel(const float* __restrict__ src,
                                                    __half* __restrict__ dst) {
    size_t i = (size_t)blockIdx.x * 256 + threadIdx.x;
    float4 v = ((const float4*)src)[i];
    uint2 hh;
    hh.x = ((uint32_t)__half_as_ushort(__float2half_rn(v.y)) << 16) | __half_as_ushort(__float2half_rn(v.x));
    hh.y = ((uint32_t)__half_as_ushort(__float2half_rn(v.w)) << 16) | __half_as_ushort(__float2half_rn(v.z));
    ((uint2*)dst)[i] = hh;
}

// ==================== cp.async 3-stage 2-pass fp16 GEMM (weights) ==========
// CTA tile 128(M) x 256(N), KC=32. 8 warps: 4(M) x 2(N), warp tile 32x128.
#define SROW 80
#define APLANE (128*SROW)       // 10240
#define BPLANE (256*SROW)       // 20480
#define SM_AHI 0
#define SM_ALO APLANE
#define SM_BHI (2*APLANE)
#define SM_STAGE (2*APLANE + BPLANE)   // 40960
#define NSTG 3
#define SM_TOTAL (NSTG*SM_STAGE)       // 122880

template<int EPI>   // 0 plain fp32 C, 1 gelu -> half planes, 2 +Res -> fp32 C
__global__ void __launch_bounds__(256, 1) gemm_mma(const __half* __restrict__ Ahi,
                                                   const __half* __restrict__ Alo,
                                                   const __half* __restrict__ Bh,
                                                   float* __restrict__ C,
                                                   const float* __restrict__ Res,
                                                   __half* __restrict__ Chi,
                                                   __half* __restrict__ Clo,
                                                   int M, int N, int K) {
    extern __shared__ char sm[];
    const uint32_t smb = smem_u32(sm);
    const int tid  = threadIdx.x;
    const int lane = tid & 31;
    const int wid  = tid >> 5;
    const int wm   = wid & 3;          // 4 warps along M (32 rows each)
    const int wn   = wid >> 2;         // 2 warps along N (128 cols each)
    const int bm = blockIdx.x, bn = blockIdx.y;

    const char* Abase = (const char*)(Ahi + (size_t)bm*128*K);
    const char* Lbase = (const char*)(Alo + (size_t)bm*128*K);
    const char* Bbase = (const char*)(Bh  + (size_t)bn*256*K);
    const size_t Kb = (size_t)K * 2;

    // copy maps: A planes 512 chunks (2/thread), B plane 1024 chunks (4/thread)
    const int ar0 = (tid + 0)   >> 2, acb0 = (tid & 3) * 16;
    const int ar1 = (tid + 256) >> 2;

    float acc[2][16][4];
#pragma unroll
    for (int i = 0; i < 2; i++)
#pragma unroll
        for (int j = 0; j < 16; j++)
#pragma unroll
            for (int q = 0; q < 4; q++) acc[i][j][q] = 0.f;

    const int NC = K >> 5;

    auto issue = [&](int st, int cc) {
        const uint32_t sb = smb + st * SM_STAGE;
        const size_t kb = (size_t)(cc << 6);
        cp16(sb + SM_AHI + ar0*SROW + acb0, Abase + (size_t)ar0*Kb + kb + acb0);
        cp16(sb + SM_AHI + ar1*SROW + acb0, Abase + (size_t)ar1*Kb + kb + acb0);
        cp16(sb + SM_ALO + ar0*SROW + acb0, Lbase + (size_t)ar0*Kb + kb + acb0);
        cp16(sb + SM_ALO + ar1*SROW + acb0, Lbase + (size_t)ar1*Kb + kb + acb0);
#pragma unroll
        for (int i = 0; i < 4; i++) {
            int c = tid + i*256;
            int r = c >> 2, cb = (c & 3) * 16;
            cp16(sb + SM_BHI + r*SROW + cb, Bbase + (size_t)r*Kb + kb + cb);
        }
    };

    issue(0, 0); CP_COMMIT();
    issue(1, 1); CP_COMMIT();

    const int a_r  = wm*32 + (lane & 15);
    const int a_kb = (lane >> 4) << 4;
    const int b_r  = wn*128 + (lane & 7);
    const int b_kb = ((lane >> 3) & 1) << 4;

    int st = 0;
    for (int c = 0; c < NC; ++c) {
        if (c + 2 < NC) {
            int s2 = st + 2; if (s2 >= NSTG) s2 -= NSTG;
            issue(s2, c + 2);
            CP_COMMIT();
        }
        {
            int remaining = NC - 1 - c;
            if (remaining >= 2)      CP_WAIT(2);
            else if (remaining == 1) CP_WAIT(1);
            else                     CP_WAIT(0);
        }
        __syncthreads();

        const uint32_t sb = smb + st * SM_STAGE;
#pragma unroll
        for (int ks = 0; ks < 2; ks++) {
            uint32_t aHi[2][4], aLo[2][4];
#pragma unroll
            for (int mt = 0; mt < 2; mt++) {
                uint32_t base = sb + (a_r + mt*16)*SROW + ks*32 + a_kb;
                ldsm_x4(aHi[mt], base + SM_AHI);
                ldsm_x4(aLo[mt], base + SM_ALO);
            }
#pragma unroll
            for (int nt = 0; nt < 16; nt++) {
                uint32_t bHi[2];
                ldsm_x2(bHi, sb + SM_BHI + (b_r + nt*8)*SROW + ks*32 + b_kb);
#pragma unroll
                for (int mt = 0; mt < 2; mt++) {
                    mma_f16(acc[mt][nt], aHi[mt], bHi);
                    mma_f16(acc[mt][nt], aLo[mt], bHi);
                }
            }
        }
        __syncthreads();
        if (++st == NSTG) st = 0;
    }

#pragma unroll
    for (int mt = 0; mt < 2; mt++) {
        int r0e = bm*128 + wm*32 + mt*16 + (lane >> 2);
#pragma unroll
        for (int nt = 0; nt < 16; nt++) {
            int col = bn*256 + wn*128 + nt*8 + (lane & 3)*2;
            float2 v0 = make_float2(acc[mt][nt][0], acc[mt][nt][1]);
            float2 v1 = make_float2(acc[mt][nt][2], acc[mt][nt][3]);
            if (EPI == 1) {
                v0.x = gelu_f(v0.x); v0.y = gelu_f(v0.y);
                v1.x = gelu_f(v1.x); v1.y = gelu_f(v1.y);
                size_t i0 = (size_t)r0e*N + col;
                size_t i1 = i0 + (size_t)8*N;
                uint32_t hh, ll;
                split2(v0, hh, ll);
                *(uint32_t*)(Chi + i0) = hh; *(uint32_t*)(Clo + i0) = ll;
                split2(v1, hh, ll);
                *(uint32_t*)(Chi + i1) = hh; *(uint32_t*)(Clo + i1) = ll;
            } else {
                float* p0 = C + (size_t)r0e*N + col;
                float* p1 = p0 + (size_t)8*N;
                if (EPI == 2) {
                    const float* q0 = Res + (size_t)r0e*N + col;
                    const float* q1 = q0 + (size_t)8*N;
                    float2 u0 = *(const float2*)q0;
                    float2 u1 = *(const float2*)q1;
                    v0.x += u0.x; v0.y += u0.y;
                    v1.x += u1.x; v1.y += u1.y;
                }
                *(float2*)p0 = v0;
                *(float2*)p1 = v1;
            }
        }
    }
}

// ==================== attention 3-pass MMA kernels (128x128) ====================
#define SM4_AHI 0
#define SM4_ALO APLANE
#define SM4_BHI (2*APLANE)
#define SM4_BLO (3*APLANE)
#define SM4_STAGE (4*APLANE)       // 40960
#define SM4_TOTAL (3*SM4_STAGE)    // 122880

// MODE 0: score  S = Q K^T  (fp32 out, causal tile skip)
// MODE 1: AV     Y = P V    (half-plane out, causal K bound, long tiles first)
template<int MODE>
__global__ void __launch_bounds__(256) attn_mma(const __half* __restrict__ Ahi_g,
                                                const __half* __restrict__ Alo_g,
                                                const __half* __restrict__ Bhi_g,
                                                const __half* __restrict__ Blo_g,
                                                float* __restrict__ Sout,
                                                __half* __restrict__ Yhi,
                                                __half* __restrict__ Ylo) {
    const int bn = blockIdx.x;
    const int bm = (MODE == 1) ? (gridDim.y - 1 - blockIdx.y) : blockIdx.y;
    if (MODE == 0 && bn > bm) return;
    const int z = blockIdx.z;
    const int b = z >> 4, h = z & 15, g = h >> 2;

    extern __shared__ char sm[];
    const uint32_t smb = smem_u32(sm);
    const int tid  = threadIdx.x;
    const int lane = tid & 31;
    const int wid  = tid >> 5;
    const int wm   = wid & 3;
    const int wn   = wid >> 2;

    const char *Abase, *Lbase, *Bbase, *BLbase;
    size_t Kab, Kbb;
    int NC;
    if (MODE == 0) {
        size_t aoff = ((size_t)(b*NH + h)*Tseq + (size_t)bm*128) * HSZ;
        size_t boff = ((size_t)(b*NG + g)*Tseq + (size_t)bn*128) * HSZ;
        Abase = (const char*)(Ahi_g + aoff);
        Lbase = (const char*)(Alo_g + aoff);
        Bbase = (const char*)(Bhi_g + boff);
        BLbase= (const char*)(Blo_g + boff);
        Kab = HSZ*2; Kbb = HSZ*2;
        NC = HSZ >> 5;
    } else {
        size_t aoff = (size_t)z*Tseq*Tseq + (size_t)bm*128*Tseq;
        size_t boff = (size_t)(b*NG + g)*HSZ*Tseq;
        Abase = (const char*)(Ahi_g + aoff);
        Lbase = (const char*)(Alo_g + aoff);
        Bbase = (const char*)(Bhi_g + boff);
        BLbase= (const char*)(Blo_g + boff);
        Kab = Tseq*2; Kbb = Tseq*2;
        NC = (bm + 1) << 2;
    }

    const int c0 = tid, c1 = tid + 256;
    const int r0 = c0 >> 2, cb0 = (c0 & 3) * 16;
    const int r1 = c1 >> 2, cb1 = (c1 & 3) * 16;

    float acc[2][8][4];
#pragma unroll
    for (int i = 0; i < 2; i++)
#pragma unroll
        for (int j = 0; j < 8; j++)
#pragma unroll
            for (int q = 0; q < 4; q++) acc[i][j][q] = 0.f;

    auto issue = [&](int st, int cc) {
        const uint32_t sb = smb + st * SM4_STAGE;
        const size_t kb = (size_t)(cc << 6);
        cp16(sb + SM4_AHI + r0*SROW + cb0, Abase + (size_t)r0*Kab + kb + cb0);
        cp16(sb + SM4_AHI + r1*SROW + cb1, Abase + (size_t)r1*Kab + kb + cb1);
        cp16(sb + SM4_ALO + r0*SROW + cb0, Lbase + (size_t)r0*Kab + kb + cb0);
        cp16(sb + SM4_ALO + r1*SROW + cb1, Lbase + (size_t)r1*Kab + kb + cb1);
        cp16(sb + SM4_BHI + r0*SROW + cb0, Bbase + (size_t)r0*Kbb + kb + cb0);
        cp16(sb + SM4_BHI + r1*SROW + cb1, Bbase + (size_t)r1*Kbb + kb + cb1);
        cp16(sb + SM4_BLO + r0*SROW + cb0, BLbase + (size_t)r0*Kbb + kb + cb0);
        cp16(sb + SM4_BLO + r1*SROW + cb1, BLbase + (size_t)r1*Kbb + kb + cb1);
    };

    issue(0, 0); CP_COMMIT();
    issue(1, 1); CP_COMMIT();

    const int a_r  = wm*32 + (lane & 15);
    const int a_kb = (lane >> 4) << 4;
    const int b_r  = wn*64 + (lane & 7);
    const int b_kb = ((lane >> 3) & 1) << 4;

    int st = 0;
    for (int c = 0; c < NC; ++c) {
        if (c + 2 < NC) {
            int s2 = st + 2; if (s2 >= 3) s2 -= 3;
            issue(s2, c + 2);
            CP_COMMIT();
        }
        {
            int remaining = NC - 1 - c;
            if (remaining >= 2)      CP_WAIT(2);
            else if (remaining == 1) CP_WAIT(1);
            else                     CP_WAIT(0);
        }
        __syncthreads();

        const uint32_t sb = smb + st * SM4_STAGE;
#pragma unroll
        for (int ks = 0; ks < 2; ks++) {
            uint32_t aHi[2][4], aLo[2][4];
#pragma unroll
            for (int mt = 0; mt < 2; mt++) {
                uint32_t base = sb + (a_r + mt*16)*SROW + ks*32 + a_kb;
                ldsm_x4(aHi[mt], base + SM4_AHI);
                ldsm_x4(aLo[mt], base + SM4_ALO);
            }
#pragma unroll
            for (int nt = 0; nt < 8; nt++) {
                uint32_t bHi[2], bLo[2];
                uint32_t base = sb + (b_r + nt*8)*SROW + ks*32 + b_kb;
                ldsm_x2(bHi, base + SM4_BHI);
                ldsm_x2(bLo, base + SM4_BLO);
#pragma unroll
                for (int mt = 0; mt < 2; mt++) {
                    mma_f16(acc[mt][nt], aHi[mt], bHi);
                    mma_f16(acc[mt][nt], aHi[mt], bLo);
                    mma_f16(acc[mt][nt], aLo[mt], bHi);
                }
            }
        }
        __syncthreads();
        if (++st == 3) st = 0;
    }

#pragma unroll
    for (int mt = 0; mt < 2; mt++) {
        int rl = bm*128 + wm*32 + mt*16 + (lane >> 2);
#pragma unroll
        for (int nt = 0; nt < 8; nt++) {
            int col = wn*64 + nt*8 + (lane & 3)*2;
            float2 v0 = make_float2(acc[mt][nt][0], acc[mt][nt][1]);
            float2 v1 = make_float2(acc[mt][nt][2], acc[mt][nt][3]);
            if (MODE == 0) {
                float* p0 = Sout + (size_t)z*Tseq*Tseq + (size_t)rl*Tseq + bn*128 + col;
                float* p1 = p0 + (size_t)8*Tseq;
                *(float2*)p0 = v0;
                *(float2*)p1 = v1;
            } else {
                size_t i0 = ((size_t)b*Tseq + rl)*Emb + h*HSZ + col;
                size_t i1 = i0 + (size_t)8*Emb;
                uint32_t hh, ll;
                split2(v0, hh, ll);
                *(uint32_t*)(Yhi + i0) = hh; *(uint32_t*)(Ylo + i0) = ll;
                split2(v1, hh, ll);
                *(uint32_t*)(Yhi + i1) = hh; *(uint32_t*)(Ylo + i1) = ll;
            }
        }
    }
}

// ---------------- embedding gather ----------------
__global__ void __launch_bounds__(256) embed_kernel(const int* __restrict__ idx,
                                                    const float* __restrict__ wte) {
    int i  = blockIdx.x * 256 + threadIdx.x;
    int bt = i >> 9;
    int e4 = i & 511;
    ((float4*)g_x)[i] = ((const float4*)wte)[(size_t)idx[bt]*512 + e4];
}

// ---------------- RMSNorm -> fp16 hi/lo planes ----------------
__global__ void __launch_bounds__(256) rmsnorm_kernel(const float* __restrict__ x,
                                                      const float* __restrict__ w,
                                                      __half* __restrict__ ohi,
                                                      __half* __restrict__ olo) {
    int row = blockIdx.x;
    int t = threadIdx.x;
    const float4* xr = (const float4*)(x + (size_t)row*Emb);
    float4 a = xr[t];
    float4 b = xr[t + 256];
    float ss = a.x*a.x + a.y*a.y + a.z*a.z + a.w*a.w
             + b.x*b.x + b.y*b.y + b.z*b.z + b.w*b.w;
#pragma unroll
    for (int o = 16; o; o >>= 1) ss += __shfl_xor_sync(0xffffffffu, ss, o);
    __shared__ float red[8];
    __shared__ float sinv;
    if ((t & 31) == 0) red[t >> 5] = ss;
    __syncthreads();
    if (t == 0) {
        float tot = red[0];
#pragma unroll
        for (int i = 1; i < 8; i++) tot += red[i];
        sinv = rsqrtf(tot * (1.0f/Emb) + EPSF);
    }
    __syncthreads();
    float inv = sinv;
    const float4* wr = (const float4*)w;
    float4 w0 = wr[t], w1 = wr[t+256];
    float4 va = make_float4(a.x*inv*w0.x, a.y*inv*w0.y, a.z*inv*w0.z, a.w*inv*w0.w);
    float4 vb = make_float4(b.x*inv*w1.x, b.y*inv*w1.y, b.z*inv*w1.z, b.w*inv*w1.w);
    uint2 hh, ll;
    uint2* hp = (uint2*)(ohi + (size_t)row*Emb);
    uint2* lp = (uint2*)(olo + (size_t)row*Emb);
    split4(va, hh, ll); hp[t]     = hh; lp[t]     = ll;
    split4(vb, hh, ll); hp[t+256] = hh; lp[t+256] = ll;
}

// ---------------- RoPE -> q/k fp16 hi/lo planes (head-major) --------------
__global__ void __launch_bounds__(256) rope_kernel() {
    int i    = blockIdx.x * 256 + threadIdx.x;
    int d    = i & 63;
    int rest = i >> 6;
    int head = rest % (NH + NG);
    int bt   = rest / (NH + NG);
    int b    = bt >> 10;
    int t    = bt & (Tseq - 1);
    size_t src = (size_t)bt*QKVD + (head < NH ? head*HSZ : NH*HSZ + (head-NH)*HSZ);
    float inv_freq = powf(10000.0f, -(float)d * (1.0f/64.0f));
    float ang = (float)t * inv_freq;
    float sn, cs;
    sincosf(ang, &sn, &cs);
    float x1 = g_qkv[src + d];
    float x2 = g_qkv[src + 64 + d];
    float r1 = x1*cs - x2*sn;
    float r2 = x2*cs + x1*sn;
    __half h1 = __float2half_rn(r1), h2 = __float2half_rn(r2);
    __half l1 = __float2half_rn(r1 - __half2float(h1));
    __half l2 = __float2half_rn(r2 - __half2float(h2));
    size_t dst;
    __half *phi, *plo;
    if (head < NH) {
        dst = ((size_t)(b*NH + head)*Tseq + t)*HSZ + d;
        phi = g_q_hi; plo = g_q_lo;
    } else {
        dst = ((size_t)(b*NG + (head - NH))*Tseq + t)*HSZ + d;
        phi = g_k_hi; plo = g_k_lo;
    }
    phi[dst] = h1;  phi[dst + 64] = h2;
    plo[dst] = l1;  plo[dst + 64] = l2;
}

// ---------------- V -> transposed fp16 hi/lo planes ----------------
__global__ void __launch_bounds__(256) vsplit_kernel() {
    int i = blockIdx.x * 256 + threadIdx.x;
    int t = i & (Tseq - 1);
    int rest = i >> 10;
    int d = rest & 127;
    rest >>= 7;
    int g = rest & 3;
    int b = rest >> 2;
    float v = g_qkv[((size_t)(b*Tseq + t))*QKVD + (NH+NG)*HSZ + g*HSZ + d];
    __half h = __float2half_rn(v);
    __half l = __float2half_rn(v - __half2float(h));
    size_t dst = ((size_t)(b*NG + g)*HSZ + d)*Tseq + t;
    g_vt_hi[dst] = h;
    g_vt_lo[dst] = l;
}

// ---------------- causal softmax -> P fp16 hi/lo planes ----------------
__global__ void __launch_bounds__(256) softmax_kernel(const float* __restrict__ S,
                                                      __half* __restrict__ Phi,
                                                      __half* __restrict__ Plo) {
    size_t z = blockIdx.x;
    int t = blockIdx.x & (Tseq - 1);
    int jlim4 = (((t >> 7) + 1) << 7) >> 2;
    const float4* row = (const float4*)(S + z*Tseq);
    int j4 = threadIdx.x;
    int j  = j4 << 2;
    bool act = j4 < jlim4;
    float4 v = make_float4(0.f, 0.f, 0.f, 0.f);
    if (act) v = row[j4];
    float s0 = (act && j   <= t) ? v.x*ASCALE : -1e30f;
    float s1 = (act && j+1 <= t) ? v.y*ASCALE : -1e30f;
    float s2 = (act && j+2 <= t) ? v.z*ASCALE : -1e30f;
    float s3 = (act && j+3 <= t) ? v.w*ASCALE : -1e30f;
    float m = fmaxf(fmaxf(s0, s1), fmaxf(s2, s3));
#pragma unroll
    for (int o = 16; o; o >>= 1) m = fmaxf(m, __shfl_xor_sync(0xffffffffu, m, o));
    __shared__ float red[8];
    __shared__ float bm2, bs;
    int tid = threadIdx.x;
    if ((tid & 31) == 0) red[tid >> 5] = m;
    __syncthreads();
    if (tid == 0) {
        float mm = red[0];
#pragma unroll
        for (int i = 1; i < 8; i++) mm = fmaxf(mm, red[i]);
        bm2 = mm;
    }
    __syncthreads();
    float mm = bm2;
    float p0 = (j   <= t) ? __expf(s0 - mm) : 0.f;
    float p1 = (j+1 <= t) ? __expf(s1 - mm) : 0.f;
    float p2 = (j+2 <= t) ? __expf(s2 - mm) : 0.f;
    float p3 = (j+3 <= t) ? __expf(s3 - mm) : 0.f;
    float sum = p0 + p1 + p2 + p3;
#pragma unroll
    for (int o = 16; o; o >>= 1) sum += __shfl_xor_sync(0xffffffffu, sum, o);
    __syncthreads();
    if ((tid & 31) == 0) red[tid >> 5] = sum;
    __syncthreads();
    if (tid == 0) {
        float tot = red[0];
#pragma unroll
        for (int i = 1; i < 8; i++) tot += red[i];
        bs = 1.0f / tot;
    }
    __syncthreads();
    float inv = bs;
    if (act) {
        float4 pv = make_float4(p0*inv, p1*inv, p2*inv, p3*inv);
        uint2 hh, ll;
        split4(pv, hh, ll);
        *(uint2*)(Phi + z*Tseq + j) = hh;
        *(uint2*)(Plo + z*Tseq + j) = ll;
    }
}

// ---------------- host entry ----------------
extern "C" void kernel_launch(void* const* d_in, const int* in_sizes, int n_in,
                              void* d_out, int out_size) {
    const int*   idx    = (const int*)  d_in[0];
    const float* wte    = (const float*)d_in[1];
    const float* qkv_w  = (const float*)d_in[2];
    const float* attn_w = (const float*)d_in[3];
    const float* fc_w   = (const float*)d_in[4];
    const float* mlp_w  = (const float*)d_in[5];
    const float* n1_w   = (const float*)d_in[6];
    const float* n2_w   = (const float*)d_in[7];
    const float* lnf_w  = (const float*)d_in[8];
    const float* lm_w   = (const float*)d_in[9];
    float* out = (float*)d_out;
    (void)in_sizes; (void)n_in; (void)out_size;

    float *px, *pqkv, *ps;
    __half *pa_hi, *pa_lo, *ph_hi, *ph_lo;
    __half *pq_hi, *pq_lo, *pk_hi, *pk_lo, *pvt_hi, *pvt_lo, *pp_hi, *pp_lo;
    __half *pwqkv, *pwattn, *pwfc, *pwmlp, *pwlm;
    cudaGetSymbolAddress((void**)&px,    g_x);
    cudaGetSymbolAddress((void**)&pqkv,  g_qkv);
    cudaGetSymbolAddress((void**)&ps,    g_s);
    cudaGetSymbolAddress((void**)&pa_hi, g_a_hi);
    cudaGetSymbolAddress((void**)&pa_lo, g_a_lo);
    cudaGetSymbolAddress((void**)&ph_hi, g_h_hi);
    cudaGetSymbolAddress((void**)&ph_lo, g_h_lo);
    cudaGetSymbolAddress((void**)&pq_hi, g_q_hi);
    cudaGetSymbolAddress((void**)&pq_lo, g_q_lo);
    cudaGetSymbolAddress((void**)&pk_hi, g_k_hi);
    cudaGetSymbolAddress((void**)&pk_lo, g_k_lo);
    cudaGetSymbolAddress((void**)&pvt_hi, g_vt_hi);
    cudaGetSymbolAddress((void**)&pvt_lo, g_vt_lo);
    cudaGetSymbolAddress((void**)&pp_hi, g_p_hi);
    cudaGetSymbolAddress((void**)&pp_lo, g_p_lo);
    cudaGetSymbolAddress((void**)&pwqkv, g_wqkv_h);
    cudaGetSymbolAddress((void**)&pwattn,g_wattn_h);
    cudaGetSymbolAddress((void**)&pwfc,  g_wfc_h);
    cudaGetSymbolAddress((void**)&pwmlp, g_wmlp_h);
    cudaGetSymbolAddress((void**)&pwlm,  g_wlm_h);

    cudaFuncSetAttribute(gemm_mma<0>, cudaFuncAttributeMaxDynamicSharedMemorySize, SM_TOTAL);
    cudaFuncSetAttribute(gemm_mma<1>, cudaFuncAttributeMaxDynamicSharedMemorySize, SM_TOTAL);
    cudaFuncSetAttribute(gemm_mma<2>, cudaFuncAttributeMaxDynamicSharedMemorySize, SM_TOTAL);
    cudaFuncSetAttribute(attn_mma<0>, cudaFuncAttributeMaxDynamicSharedMemorySize, SM4_TOTAL);
    cudaFuncSetAttribute(attn_mma<1>, cudaFuncAttributeMaxDynamicSharedMemorySize, SM4_TOTAL);

    // ---- one-time weight fp16 planes ----
    wconv_kernel<<<(int)(((size_t)NL*QKVD*Emb)/4/256), 256>>>(qkv_w,  pwqkv);
    wconv_kernel<<<(int)(((size_t)NL*Emb*(NH*HSZ))/4/256), 256>>>(attn_w, pwattn);
    wconv_kernel<<<(int)(((size_t)NL*FFD*Emb)/4/256), 256>>>(fc_w,   pwfc);
    wconv_kernel<<<(int)(((size_t)NL*Emb*FFD)/4/256), 256>>>(mlp_w,  pwmlp);
    wconv_kernel<<<(int)(((size_t)Voc*Emb)/4/256), 256>>>(lm_w,   pwlm);

    embed_kernel<<<NTOK*Emb/4/256, 256>>>(idx, wte);

    for (int l = 0; l < NL; l++) {
        rmsnorm_kernel<<<NTOK, 256>>>(px, n1_w + (size_t)l*Emb, pa_hi, pa_lo);
        gemm_mma<0><<<dim3(NTOK/128, QKVD/256), 256, SM_TOTAL>>>(
            pa_hi, pa_lo, pwqkv + (size_t)l*QKVD*Emb, pqkv, nullptr, nullptr, nullptr,
            NTOK, QKVD, Emb);
        rope_kernel<<<NTOK*(NH+NG)*64/256, 256>>>();
        vsplit_kernel<<<Bsz*NG*HSZ*Tseq/256, 256>>>();
        attn_mma<0><<<dim3(Tseq/128, Tseq/128, Bsz*NH), 256, SM4_TOTAL>>>(
            pq_hi, pq_lo, pk_hi, pk_lo, ps, nullptr, nullptr);
        softmax_kernel<<<Bsz*NH*Tseq, 256>>>(ps, pp_hi, pp_lo);
        attn_mma<1><<<dim3(1, Tseq/128, Bsz*NH), 256, SM4_TOTAL>>>(
            pp_hi, pp_lo, pvt_hi, pvt_lo, nullptr, pa_hi, pa_lo);
        gemm_mma<2><<<dim3(NTOK/128, Emb/256), 256, SM_TOTAL>>>(
            pa_hi, pa_lo, pwattn + (size_t)l*Emb*(NH*HSZ), px, px, nullptr, nullptr,
            NTOK, Emb, NH*HSZ);
        rmsnorm_kernel<<<NTOK, 256>>>(px, n2_w + (size_t)l*Emb, pa_hi, pa_lo);
        gemm_mma<1><<<dim3(NTOK/128, FFD/256), 256, SM_TOTAL>>>(
            pa_hi, pa_lo, pwfc + (size_t)l*FFD*Emb, nullptr, nullptr, ph_hi, ph_lo,
            NTOK, FFD, Emb);
        gemm_mma<2><<<dim3(NTOK/128, Emb/256), 256, SM_TOTAL>>>(
            ph_hi, ph_lo, pwmlp + (size_t)l*Emb*FFD, px, px, nullptr, nullptr,
            NTOK, Emb, FFD);
    }

    rmsnorm_kernel<<<NTOK, 256>>>(px, lnf_w, pa_hi, pa_lo);
    gemm_mma<0><<<dim3(NTOK/128, Voc/256), 256, SM_TOTAL>>>(
        pa_hi, pa_lo, pwlm, out, nullptr, nullptr, nullptr, NTOK, Voc, Emb);
}

// round 13
// speedup vs baseline: 1.0763x; 1.0763x over previous
#include <cuda_runtime.h>
#include <cuda_fp16.h>
#include <math.h>
#include <stdint.h>

#define Bsz  2
#define Tseq 1024
#define Emb  2048
#define NH   16
#define NG   4
#define HSZ  128
#define NL   4
#define Voc  32000
#define FFD  8192
#define NTOK (Bsz*Tseq)                 // 2048
#define QKVD ((NH+2*NG)*HSZ)            // 3072
#define EPSF 1e-5f
#define ASCALE 0.08838834764831845f     // 1/sqrt(128)

// ---------------- scratch (device globals; no allocation allowed) ----------
__device__ __align__(128) float g_x  [NTOK*Emb];
__device__ __align__(128) float g_qkv[NTOK*QKVD];
__device__ __align__(128) float g_s  [(size_t)Bsz*NH*Tseq*Tseq];

// activation fp16 planes (hi/lo split)
__device__ __align__(128) __half g_a_hi[NTOK*Emb];
__device__ __align__(128) __half g_a_lo[NTOK*Emb];
__device__ __align__(128) __half g_h_hi[NTOK*FFD];
__device__ __align__(128) __half g_h_lo[NTOK*FFD];

// attention fp16 planes
__device__ __align__(128) __half g_q_hi[(size_t)Bsz*NH*Tseq*HSZ];
__device__ __align__(128) __half g_q_lo[(size_t)Bsz*NH*Tseq*HSZ];
__device__ __align__(128) __half g_k_hi[(size_t)Bsz*NG*Tseq*HSZ];
__device__ __align__(128) __half g_k_lo[(size_t)Bsz*NG*Tseq*HSZ];
__device__ __align__(128) __half g_vt_hi[(size_t)Bsz*NG*HSZ*Tseq];
__device__ __align__(128) __half g_vt_lo[(size_t)Bsz*NG*HSZ*Tseq];
__device__ __align__(128) __half g_p_hi[(size_t)Bsz*NH*Tseq*Tseq];

// weight fp16 planes (converted once per launch)
__device__ __align__(128) __half g_wqkv_h[(size_t)NL*QKVD*Emb];
__device__ __align__(128) __half g_wattn_h[(size_t)NL*Emb*(NH*HSZ)];
__device__ __align__(128) __half g_wfc_h [(size_t)NL*FFD*Emb];
__device__ __align__(128) __half g_wmlp_h[(size_t)NL*Emb*FFD];
__device__ __align__(128) __half g_wlm_h [(size_t)Voc*Emb];

// ==================== helpers ====================
__device__ __forceinline__ uint32_t smem_u32(const void* p) {
    uint32_t a;
    asm("{ .reg .u64 t; cvta.to.shared.u64 t, %1; cvt.u32.u64 %0, t; }" : "=r"(a) : "l"(p));
    return a;
}
__device__ __forceinline__ void ldsm_x4(uint32_t* r, uint32_t addr) {
    asm volatile("ldmatrix.sync.aligned.m8n8.x4.shared.b16 {%0,%1,%2,%3}, [%4];"
        : "=r"(r[0]), "=r"(r[1]), "=r"(r[2]), "=r"(r[3]) : "r"(addr));
}
__device__ __forceinline__ void ldsm_x2(uint32_t* r, uint32_t addr) {
    asm volatile("ldmatrix.sync.aligned.m8n8.x2.shared.b16 {%0,%1}, [%2];"
        : "=r"(r[0]), "=r"(r[1]) : "r"(addr));
}
__device__ __forceinline__ void mma_f16(float* d, const uint32_t* a, const uint32_t* b) {
    asm volatile(
        "mma.sync.aligned.m16n8k16.row.col.f32.f16.f16.f32 "
        "{%0,%1,%2,%3}, {%4,%5,%6,%7}, {%8,%9}, {%0,%1,%2,%3};"
        : "+f"(d[0]), "+f"(d[1]), "+f"(d[2]), "+f"(d[3])
        : "r"(a[0]), "r"(a[1]), "r"(a[2]), "r"(a[3]), "r"(b[0]), "r"(b[1]));
}
__device__ __forceinline__ void cp16(uint32_t saddr, const void* gptr) {
    asm volatile("cp.async.cg.shared.global [%0], [%1], 16;" :: "r"(saddr), "l"(gptr));
}
#define CP_COMMIT() asm volatile("cp.async.commit_group;" ::: "memory")
#define CP_WAIT(n)  asm volatile("cp.async.wait_group %0;" :: "n"(n) : "memory")

__device__ __forceinline__ float gelu_f(float x) {
    return 0.5f*x*(1.0f + tanhf(0.7978845608028654f*(x + 0.044715f*x*x*x)));
}
__device__ __forceinline__ void split4(float4 v, uint2& hh, uint2& ll) {
    __half h0 = __float2half_rn(v.x);
    __half h1 = __float2half_rn(v.y);
    __half h2 = __float2half_rn(v.z);
    __half h3 = __float2half_rn(v.w);
    __half l0 = __float2half_rn(v.x - __half2float(h0));
    __half l1 = __float2half_rn(v.y - __half2float(h1));
    __half l2 = __float2half_rn(v.z - __half2float(h2));
    __half l3 = __float2half_rn(v.w - __half2float(h3));
    hh.x = ((uint32_t)__half_as_ushort(h1) << 16) | __half_as_ushort(h0);
    hh.y = ((uint32_t)__half_as_ushort(h3) << 16) | __half_as_ushort(h2);
    ll.x = ((uint32_t)__half_as_ushort(l1) << 16) | __half_as_ushort(l0);
    ll.y = ((uint32_t)__half_as_ushort(l3) << 16) | __half_as_ushort(l2);
}
__device__ __forceinline__ void split2(float2 v, uint32_t& hh, uint32_t& ll) {
    __half h0 = __float2half_rn(v.x);
    __half h1 = __float2half_rn(v.y);
    __half l0 = __float2half_rn(v.x - __half2float(h0));
    __half l1 = __float2half_rn(v.y - __half2float(h1));
    hh = ((uint32_t)__half_as_ushort(h1) << 16) | __half_as_ushort(h0);
    ll = ((uint32_t)__half_as_ushort(l1) << 16) | __half_as_ushort(l0);
}

// ---------------- weight fp32 -> fp16 convert ----------------
__global__ void __launch_bounds__(256) wconv_kernel(const float* __restrict__ src,
                                                    __half* __restrict__ dst) {
    size_t i = (size_t)blockIdx.x * 256 + threadIdx.x;
    float4 v = ((const float4*)src)[i];
    uint2 hh;
    hh.x = ((uint32_t)__half_as_ushort(__float2half_rn(v.y)) << 16) | __half_as_ushort(__float2half_rn(v.x));
    hh.y = ((uint32_t)__half_as_ushort(__float2half_rn(v.w)) << 16) | __half_as_ushort(__float2half_rn(v.z));
    ((uint2*)dst)[i] = hh;
}

// ==================== cp.async 3-stage 2-pass fp16 GEMM (weights) ==========
// ROUND-10 CONFIG (proven): CTA 128x128, KC=32, 3 stages, 92KB -> 2 CTA/SM.
#define SROW 80
#define PLANE (128*SROW)        // 10240
#define SM_AHI 0
#define SM_ALO PLANE
#define SM_BHI (2*PLANE)
#define SM_STAGE (3*PLANE)      // 30720
#define NSTG 3
#define SM_TOTAL (NSTG*SM_STAGE) // 92160

template<int EPI>   // 0 plain fp32 C, 1 gelu -> half planes, 2 +Res -> fp32 C
__global__ void __launch_bounds__(256) gemm_mma(const __half* __restrict__ Ahi,
                                                const __half* __restrict__ Alo,
                                                const __half* __restrict__ Bh,
                                                float* __restrict__ C,
                                                const float* __restrict__ Res,
                                                __half* __restrict__ Chi,
                                                __half* __restrict__ Clo,
                                                int M, int N, int K) {
    extern __shared__ char sm[];
    const uint32_t smb = smem_u32(sm);
    const int tid  = threadIdx.x;
    const int lane = tid & 31;
    const int wid  = tid >> 5;
    const int wm   = wid & 3;
    const int wn   = wid >> 2;
    const int bm = blockIdx.x, bn = blockIdx.y;

    const char* Abase = (const char*)(Ahi + (size_t)bm*128*K);
    const char* Lbase = (const char*)(Alo + (size_t)bm*128*K);
    const char* Bbase = (const char*)(Bh  + (size_t)bn*128*K);
    const size_t Kb = (size_t)K * 2;

    const int c0 = tid, c1 = tid + 256;
    const int r0 = c0 >> 2, cb0 = (c0 & 3) * 16;
    const int r1 = c1 >> 2, cb1 = (c1 & 3) * 16;

    float acc[2][8][4];
#pragma unroll
    for (int i = 0; i < 2; i++)
#pragma unroll
        for (int j = 0; j < 8; j++)
#pragma unroll
            for (int q = 0; q < 4; q++) acc[i][j][q] = 0.f;

    const int NC = K >> 5;

    auto issue = [&](int st, int cc) {
        const uint32_t sb = smb + st * SM_STAGE;
        const size_t kb = (size_t)(cc << 6);
        cp16(sb + SM_AHI + r0*SROW + cb0, Abase + (size_t)r0*Kb + kb + cb0);
        cp16(sb + SM_AHI + r1*SROW + cb1, Abase + (size_t)r1*Kb + kb + cb1);
        cp16(sb + SM_ALO + r0*SROW + cb0, Lbase + (size_t)r0*Kb + kb + cb0);
        cp16(sb + SM_ALO + r1*SROW + cb1, Lbase + (size_t)r1*Kb + kb + cb1);
        cp16(sb + SM_BHI + r0*SROW + cb0, Bbase + (size_t)r0*Kb + kb + cb0);
        cp16(sb + SM_BHI + r1*SROW + cb1, Bbase + (size_t)r1*Kb + kb + cb1);
    };

    issue(0, 0); CP_COMMIT();
    issue(1, 1); CP_COMMIT();

    const int a_r  = wm*32 + (lane & 15);
    const int a_kb = (lane >> 4) << 4;
    const int b_r  = wn*64 + (lane & 7);
    const int b_kb = ((lane >> 3) & 1) << 4;

    int st = 0;
    for (int c = 0; c < NC; ++c) {
        if (c + 2 < NC) {
            int s2 = st + 2; if (s2 >= NSTG) s2 -= NSTG;
            issue(s2, c + 2);
            CP_COMMIT();
        }
        {
            int remaining = NC - 1 - c;
            if (remaining >= 2)      CP_WAIT(2);
            else if (remaining == 1) CP_WAIT(1);
            else                     CP_WAIT(0);
        }
        __syncthreads();

        const uint32_t sb = smb + st * SM_STAGE;
#pragma unroll
        for (int ks = 0; ks < 2; ks++) {
            uint32_t aHi[2][4], aLo[2][4];
#pragma unroll
            for (int mt = 0; mt < 2; mt++) {
                uint32_t base = sb + (a_r + mt*16)*SROW + ks*32 + a_kb;
                ldsm_x4(aHi[mt], base + SM_AHI);
                ldsm_x4(aLo[mt], base + SM_ALO);
            }
            uint32_t bHi[8][2];
#pragma unroll
            for (int nt = 0; nt < 8; nt++) {
                uint32_t base = sb + (b_r + nt*8)*SROW + ks*32 + b_kb;
                ldsm_x2(bHi[nt], base + SM_BHI);
            }
#pragma unroll
            for (int mt = 0; mt < 2; mt++)
#pragma unroll
                for (int nt = 0; nt < 8; nt++) {
                    mma_f16(acc[mt][nt], aHi[mt], bHi[nt]);
                    mma_f16(acc[mt][nt], aLo[mt], bHi[nt]);
                }
        }
        __syncthreads();
        if (++st == NSTG) st = 0;
    }

#pragma unroll
    for (int mt = 0; mt < 2; mt++) {
        int r0e = bm*128 + wm*32 + mt*16 + (lane >> 2);
#pragma unroll
        for (int nt = 0; nt < 8; nt++) {
            int col = bn*128 + wn*64 + nt*8 + (lane & 3)*2;
            float2 v0 = make_float2(acc[mt][nt][0], acc[mt][nt][1]);
            float2 v1 = make_float2(acc[mt][nt][2], acc[mt][nt][3]);
            if (EPI == 1) {
                v0.x = gelu_f(v0.x); v0.y = gelu_f(v0.y);
                v1.x = gelu_f(v1.x); v1.y = gelu_f(v1.y);
                size_t i0 = (size_t)r0e*N + col;
                size_t i1 = i0 + (size_t)8*N;
                uint32_t hh, ll;
                split2(v0, hh, ll);
                *(uint32_t*)(Chi + i0) = hh; *(uint32_t*)(Clo + i0) = ll;
                split2(v1, hh, ll);
                *(uint32_t*)(Chi + i1) = hh; *(uint32_t*)(Clo + i1) = ll;
            } else {
                float* p0 = C + (size_t)r0e*N + col;
                float* p1 = p0 + (size_t)8*N;
                if (EPI == 2) {
                    const float* q0 = Res + (size_t)r0e*N + col;
                    const float* q1 = q0 + (size_t)8*N;
                    float2 u0 = *(const float2*)q0;
                    float2 u1 = *(const float2*)q1;
                    v0.x += u0.x; v0.y += u0.y;
                    v1.x += u1.x; v1.y += u1.y;
                }
                *(float2*)p0 = v0;
                *(float2*)p1 = v1;
            }
        }
    }
}

// ==================== score MMA: 4-plane, 3-pass (Q,K hi/lo) ====================
#define SM4_AHI 0
#define SM4_ALO PLANE
#define SM4_BHI (2*PLANE)
#define SM4_BLO (3*PLANE)
#define SM4_STAGE (4*PLANE)        // 40960
#define SM4_TOTAL (3*SM4_STAGE)    // 122880

__global__ void __launch_bounds__(256) score_mma(const __half* __restrict__ Qhi,
                                                 const __half* __restrict__ Qlo,
                                                 const __half* __restrict__ Khi,
                                                 const __half* __restrict__ Klo,
                                                 float* __restrict__ Sout) {
    const int bn = blockIdx.x;
    const int bm = blockIdx.y;
    if (bn > bm) return;
    const int z = blockIdx.z;
    const int b = z >> 4, h = z & 15, g = h >> 2;

    extern __shared__ char sm[];
    const uint32_t smb = smem_u32(sm);
    const int tid  = threadIdx.x;
    const int lane = tid & 31;
    const int wid  = tid >> 5;
    const int wm   = wid & 3;
    const int wn   = wid >> 2;

    size_t aoff = ((size_t)(b*NH + h)*Tseq + (size_t)bm*128) * HSZ;
    size_t boff = ((size_t)(b*NG + g)*Tseq + (size_t)bn*128) * HSZ;
    const char* Abase = (const char*)(Qhi + aoff);
    const char* Lbase = (const char*)(Qlo + aoff);
    const char* Bbase = (const char*)(Khi + boff);
    const char* BLbase= (const char*)(Klo + boff);
    const size_t Kb = HSZ*2;
    const int NC = HSZ >> 5;    // 4

    const int c0 = tid, c1 = tid + 256;
    const int r0 = c0 >> 2, cb0 = (c0 & 3) * 16;
    const int r1 = c1 >> 2, cb1 = (c1 & 3) * 16;

    float acc[2][8][4];
#pragma unroll
    for (int i = 0; i < 2; i++)
#pragma unroll
        for (int j = 0; j < 8; j++)
#pragma unroll
            for (int q = 0; q < 4; q++) acc[i][j][q] = 0.f;

    auto issue = [&](int st, int cc) {
        const uint32_t sb = smb + st * SM4_STAGE;
        const size_t kb = (size_t)(cc << 6);
        cp16(sb + SM4_AHI + r0*SROW + cb0, Abase + (size_t)r0*Kb + kb + cb0);
        cp16(sb + SM4_AHI + r1*SROW + cb1, Abase + (size_t)r1*Kb + kb + cb1);
        cp16(sb + SM4_ALO + r0*SROW + cb0, Lbase + (size_t)r0*Kb + kb + cb0);
        cp16(sb + SM4_ALO + r1*SROW + cb1, Lbase + (size_t)r1*Kb + kb + cb1);
        cp16(sb + SM4_BHI + r0*SROW + cb0, Bbase + (size_t)r0*Kb + kb + cb0);
        cp16(sb + SM4_BHI + r1*SROW + cb1, Bbase + (size_t)r1*Kb + kb + cb1);
        cp16(sb + SM4_BLO + r0*SROW + cb0, BLbase + (size_t)r0*Kb + kb + cb0);
        cp16(sb + SM4_BLO + r1*SROW + cb1, BLbase + (size_t)r1*Kb + kb + cb1);
    };

    issue(0, 0); CP_COMMIT();
    issue(1, 1); CP_COMMIT();

    const int a_r  = wm*32 + (lane & 15);
    const int a_kb = (lane >> 4) << 4;
    const int b_r  = wn*64 + (lane & 7);
    const int b_kb = ((lane >> 3) & 1) << 4;

    int st = 0;
    for (int c = 0; c < NC; ++c) {
        if (c + 2 < NC) {
            int s2 = st + 2; if (s2 >= 3) s2 -= 3;
            issue(s2, c + 2);
            CP_COMMIT();
        }
        {
            int remaining = NC - 1 - c;
            if (remaining >= 2)      CP_WAIT(2);
            else if (remaining == 1) CP_WAIT(1);
            else                     CP_WAIT(0);
        }
        __syncthreads();

        const uint32_t sb = smb + st * SM4_STAGE;
#pragma unroll
        for (int ks = 0; ks < 2; ks++) {
            uint32_t aHi[2][4], aLo[2][4];
#pragma unroll
            for (int mt = 0; mt < 2; mt++) {
                uint32_t base = sb + (a_r + mt*16)*SROW + ks*32 + a_kb;
                ldsm_x4(aHi[mt], base + SM4_AHI);
                ldsm_x4(aLo[mt], base + SM4_ALO);
            }
#pragma unroll
            for (int nt = 0; nt < 8; nt++) {
                uint32_t bHi[2], bLo[2];
                uint32_t base = sb + (b_r + nt*8)*SROW + ks*32 + b_kb;
                ldsm_x2(bHi, base + SM4_BHI);
                ldsm_x2(bLo, base + SM4_BLO);
#pragma unroll
                for (int mt = 0; mt < 2; mt++) {
                    mma_f16(acc[mt][nt], aHi[mt], bHi);
                    mma_f16(acc[mt][nt], aHi[mt], bLo);
                    mma_f16(acc[mt][nt], aLo[mt], bHi);
                }
            }
        }
        __syncthreads();
        if (++st == 3) st = 0;
    }

#pragma unroll
    for (int mt = 0; mt < 2; mt++) {
        int rl = bm*128 + wm*32 + mt*16 + (lane >> 2);
#pragma unroll
        for (int nt = 0; nt < 8; nt++) {
            int col = wn*64 + nt*8 + (lane & 3)*2;
            float* p0 = Sout + (size_t)z*Tseq*Tseq + (size_t)rl*Tseq + bn*128 + col;
            float* p1 = p0 + (size_t)8*Tseq;
            *(float2*)p0 = make_float2(acc[mt][nt][0], acc[mt][nt][1]);
            *(float2*)p1 = make_float2(acc[mt][nt][2], acc[mt][nt][3]);
        }
    }
}

// ==================== AV MMA: 3-plane (P fp16; V hi/lo), 2-pass ====================
// stage = 3 planes -> 92KB total -> 2 CTA/SM. Long query tiles launch first.
#define SM3_A   0
#define SM3_BHI PLANE
#define SM3_BLO (2*PLANE)
#define SM3_STAGE (3*PLANE)        // 30720
#define SM3_TOTAL (3*SM3_STAGE)    // 92160

__global__ void __launch_bounds__(256) av_mma(const __half* __restrict__ P,
                                              const __half* __restrict__ Vhi,
                                              const __half* __restrict__ Vlo,
                                              __half* __restrict__ Yhi,
                                              __half* __restrict__ Ylo) {
    const int bm = (int)(gridDim.y - 1 - blockIdx.y);    // long tiles first
    const int z = blockIdx.z;
    const int b = z >> 4, h = z & 15, g = h >> 2;

    extern __shared__ char sm[];
    const uint32_t smb = smem_u32(sm);
    const int tid  = threadIdx.x;
    const int lane = tid & 31;
    const int wid  = tid >> 5;
    const int wm   = wid & 3;
    const int wn   = wid >> 2;

    size_t aoff = (size_t)z*Tseq*Tseq + (size_t)bm*128*Tseq;
    size_t boff = (size_t)(b*NG + g)*HSZ*Tseq;
    const char* Abase = (const char*)(P + aoff);
    const char* Bbase = (const char*)(Vhi + boff);
    const char* BLbase= (const char*)(Vlo + boff);
    const size_t Kb = Tseq*2;
    const int NC = (bm + 1) << 2;          // 4..32

    const int c0 = tid, c1 = tid + 256;
    const int r0 = c0 >> 2, cb0 = (c0 & 3) * 16;
    const int r1 = c1 >> 2, cb1 = (c1 & 3) * 16;

    float acc[2][8][4];
#pragma unroll
    for (int i = 0; i < 2; i++)
#pragma unroll
        for (int j = 0; j < 8; j++)
#pragma unroll
            for (int q = 0; q < 4; q++) acc[i][j][q] = 0.f;

    auto issue = [&](int st, int cc) {
        const uint32_t sb = smb + st * SM3_STAGE;
        const size_t kb = (size_t)(cc << 6);
        cp16(sb + SM3_A   + r0*SROW + cb0, Abase + (size_t)r0*Kb + kb + cb0);
        cp16(sb + SM3_A   + r1*SROW + cb1, Abase + (size_t)r1*Kb + kb + cb1);
        cp16(sb + SM3_BHI + r0*SROW + cb0, Bbase + (size_t)r0*Kb + kb + cb0);
        cp16(sb + SM3_BHI + r1*SROW + cb1, Bbase + (size_t)r1*Kb + kb + cb1);
        cp16(sb + SM3_BLO + r0*SROW + cb0, BLbase + (size_t)r0*Kb + kb + cb0);
        cp16(sb + SM3_BLO + r1*SROW + cb1, BLbase + (size_t)r1*Kb + kb + cb1);
    };

    issue(0, 0); CP_COMMIT();
    issue(1, 1); CP_COMMIT();

    const int a_r  = wm*32 + (lane & 15);
    const int a_kb = (lane >> 4) << 4;
    const int b_r  = wn*64 + (lane & 7);
    const int b_kb = ((lane >> 3) & 1) << 4;

    int st = 0;
    for (int c = 0; c < NC; ++c) {
        if (c + 2 < NC) {
            int s2 = st + 2; if (s2 >= 3) s2 -= 3;
            issue(s2, c + 2);
            CP_COMMIT();
        }
        {
            int remaining = NC - 1 - c;
            if (remaining >= 2)      CP_WAIT(2);
            else if (remaining == 1) CP_WAIT(1);
            else                     CP_WAIT(0);
        }
        __syncthreads();

        const uint32_t sb = smb + st * SM3_STAGE;
#pragma unroll
        for (int ks = 0; ks < 2; ks++) {
            uint32_t aF[2][4];
#pragma unroll
            for (int mt = 0; mt < 2; mt++) {
                ldsm_x4(aF[mt], sb + SM3_A + (a_r + mt*16)*SROW + ks*32 + a_kb);
            }
#pragma unroll
            for (int nt = 0; nt < 8; nt++) {
                uint32_t bHi[2], bLo[2];
                uint32_t base = sb + (b_r + nt*8)*SROW + ks*32 + b_kb;
                ldsm_x2(bHi, base + SM3_BHI);
                ldsm_x2(bLo, base + SM3_BLO);
#pragma unroll
                for (int mt = 0; mt < 2; mt++) {
                    mma_f16(acc[mt][nt], aF[mt], bHi);
                    mma_f16(acc[mt][nt], aF[mt], bLo);
                }
            }
        }
        __syncthreads();
        if (++st == 3) st = 0;
    }

#pragma unroll
    for (int mt = 0; mt < 2; mt++) {
        int rl = bm*128 + wm*32 + mt*16 + (lane >> 2);
#pragma unroll
        for (int nt = 0; nt < 8; nt++) {
            int col = wn*64 + nt*8 + (lane & 3)*2;
            size_t i0 = ((size_t)b*Tseq + rl)*Emb + h*HSZ + col;
            size_t i1 = i0 + (size_t)8*Emb;
            uint32_t hh, ll;
            split2(make_float2(acc[mt][nt][0], acc[mt][nt][1]), hh, ll);
            *(uint32_t*)(Yhi + i0) = hh; *(uint32_t*)(Ylo + i0) = ll;
            split2(make_float2(acc[mt][nt][2], acc[mt][nt][3]), hh, ll);
            *(uint32_t*)(Yhi + i1) = hh; *(uint32_t*)(Ylo + i1) = ll;
        }
    }
}

// ---------------- embedding gather ----------------
__global__ void __launch_bounds__(256) embed_kernel(const int* __restrict__ idx,
                                                    const float* __restrict__ wte) {
    int i  = blockIdx.x * 256 + threadIdx.x;
    int bt = i >> 9;
    int e4 = i & 511;
    ((float4*)g_x)[i] = ((const float4*)wte)[(size_t)idx[bt]*512 + e4];
}

// ---------------- RMSNorm -> fp16 hi/lo planes ----------------
__global__ void __launch_bounds__(256) rmsnorm_kernel(const float* __restrict__ x,
                                                      const float* __restrict__ w,
                                                      __half* __restrict__ ohi,
                                                      __half* __restrict__ olo) {
    int row = blockIdx.x;
    int t = threadIdx.x;
    const float4* xr = (const float4*)(x + (size_t)row*Emb);
    float4 a = xr[t];
    float4 b = xr[t + 256];
    float ss = a.x*a.x + a.y*a.y + a.z*a.z + a.w*a.w
             + b.x*b.x + b.y*b.y + b.z*b.z + b.w*b.w;
#pragma unroll
    for (int o = 16; o; o >>= 1) ss += __shfl_xor_sync(0xffffffffu, ss, o);
    __shared__ float red[8];
    __shared__ float sinv;
    if ((t & 31) == 0) red[t >> 5] = ss;
    __syncthreads();
    if (t == 0) {
        float tot = red[0];
#pragma unroll
        for (int i = 1; i < 8; i++) tot += red[i];
        sinv = rsqrtf(tot * (1.0f/Emb) + EPSF);
    }
    __syncthreads();
    float inv = sinv;
    const float4* wr = (const float4*)w;
    float4 w0 = wr[t], w1 = wr[t+256];
    float4 va = make_float4(a.x*inv*w0.x, a.y*inv*w0.y, a.z*inv*w0.z, a.w*inv*w0.w);
    float4 vb = make_float4(b.x*inv*w1.x, b.y*inv*w1.y, b.z*inv*w1.z, b.w*inv*w1.w);
    uint2 hh, ll;
    uint2* hp = (uint2*)(ohi + (size_t)row*Emb);
    uint2* lp = (uint2*)(olo + (size_t)row*Emb);
    split4(va, hh, ll); hp[t]     = hh; lp[t]     = ll;
    split4(vb, hh, ll); hp[t+256] = hh; lp[t+256] = ll;
}

// ---------------- RoPE -> q/k fp16 hi/lo planes (head-major) --------------
__global__ void __launch_bounds__(256) rope_kernel() {
    int i    = blockIdx.x * 256 + threadIdx.x;
    int d    = i & 63;
    int rest = i >> 6;
    int head = rest % (NH + NG);
    int bt   = rest / (NH + NG);
    int b    = bt >> 10;
    int t    = bt & (Tseq - 1);
    size_t src = (size_t)bt*QKVD + (head < NH ? head*HSZ : NH*HSZ + (head-NH)*HSZ);
    float inv_freq = powf(10000.0f, -(float)d * (1.0f/64.0f));
    float ang = (float)t * inv_freq;
    float sn, cs;
    sincosf(ang, &sn, &cs);
    float x1 = g_qkv[src + d];
    float x2 = g_qkv[src + 64 + d];
    float r1 = x1*cs - x2*sn;
    float r2 = x2*cs + x1*sn;
    __half h1 = __float2half_rn(r1), h2 = __float2half_rn(r2);
    __half l1 = __float2half_rn(r1 - __half2float(h1));
    __half l2 = __float2half_rn(r2 - __half2float(h2));
    size_t dst;
    __half *phi, *plo;
    if (head < NH) {
        dst = ((size_t)(b*NH + head)*Tseq + t)*HSZ + d;
        phi = g_q_hi; plo = g_q_lo;
    } else {
        dst = ((size_t)(b*NG + (head - NH))*Tseq + t)*HSZ + d;
        phi = g_k_hi; plo = g_k_lo;
    }
    phi[dst] = h1;  phi[dst + 64] = h2;
    plo[dst] = l1;  plo[dst + 64] = l2;
}

// ---------------- V -> transposed fp16 hi/lo planes ----------------
__global__ void __launch_bounds__(256) vsplit_kernel() {
    int i = blockIdx.x * 256 + threadIdx.x;
    int t = i & (Tseq - 1);
    int rest = i >> 10;
    int d = rest & 127;
    rest >>= 7;
    int g = rest & 3;
    int b = rest >> 2;
    float v = g_qkv[((size_t)(b*Tseq + t))*QKVD + (NH+NG)*HSZ + g*HSZ + d];
    __half h = __float2half_rn(v);
    __half l = __float2half_rn(v - __half2float(h));
    size_t dst = ((size_t)(b*NG + g)*HSZ + d)*Tseq + t;
    g_vt_hi[dst] = h;
    g_vt_lo[dst] = l;
}

// ---------------- causal softmax -> P fp16 (rounded) ----------------
__global__ void __launch_bounds__(256) softmax_kernel(const float* __restrict__ S,
                                                      __half* __restrict__ Phi) {
    size_t z = blockIdx.x;
    int t = blockIdx.x & (Tseq - 1);
    int jlim4 = (((t >> 7) + 1) << 7) >> 2;
    const float4* row = (const float4*)(S + z*Tseq);
    int j4 = threadIdx.x;
    int j  = j4 << 2;
    bool act = j4 < jlim4;
    float4 v = make_float4(0.f, 0.f, 0.f, 0.f);
    if (act) v = row[j4];
    float s0 = (act && j   <= t) ? v.x*ASCALE : -1e30f;
    float s1 = (act && j+1 <= t) ? v.y*ASCALE : -1e30f;
    float s2 = (act && j+2 <= t) ? v.z*ASCALE : -1e30f;
    float s3 = (act && j+3 <= t) ? v.w*ASCALE : -1e30f;
    float m = fmaxf(fmaxf(s0, s1), fmaxf(s2, s3));
#pragma unroll
    for (int o = 16; o; o >>= 1) m = fmaxf(m, __shfl_xor_sync(0xffffffffu, m, o));
    __shared__ float red[8];
    __shared__ float bm2, bs;
    int tid = threadIdx.x;
    if ((tid & 31) == 0) red[tid >> 5] = m;
    __syncthreads();
    if (tid == 0) {
        float mm = red[0];
#pragma unroll
        for (int i = 1; i < 8; i++) mm = fmaxf(mm, red[i]);
        bm2 = mm;
    }
    __syncthreads();
    float mm = bm2;
    float p0 = (j   <= t) ? __expf(s0 - mm) : 0.f;
    float p1 = (j+1 <= t) ? __expf(s1 - mm) : 0.f;
    float p2 = (j+2 <= t) ? __expf(s2 - mm) : 0.f;
    float p3 = (j+3 <= t) ? __expf(s3 - mm) : 0.f;
    float sum = p0 + p1 + p2 + p3;
#pragma unroll
    for (int o = 16; o; o >>= 1) sum += __shfl_xor_sync(0xffffffffu, sum, o);
    __syncthreads();
    if ((tid & 31) == 0) red[tid >> 5] = sum;
    __syncthreads();
    if (tid == 0) {
        float tot = red[0];
#pragma unroll
        for (int i = 1; i < 8; i++) tot += red[i];
        bs = 1.0f / tot;
    }
    __syncthreads();
    float inv = bs;
    if (act) {
        uint2 hh;
        hh.x = ((uint32_t)__half_as_ushort(__float2half_rn(p1*inv)) << 16)
             |  __half_as_ushort(__float2half_rn(p0*inv));
        hh.y = ((uint32_t)__half_as_ushort(__float2half_rn(p3*inv)) << 16)
             |  __half_as_ushort(__float2half_rn(p2*inv));
        *(uint2*)(Phi + z*Tseq + j) = hh;
    }
}

// ---------------- host entry ----------------
extern "C" void kernel_launch(void* const* d_in, const int* in_sizes, int n_in,
                              void* d_out, int out_size) {
    const int*   idx    = (const int*)  d_in[0];
    const float* wte    = (const float*)d_in[1];
    const float* qkv_w  = (const float*)d_in[2];
    const float* attn_w = (const float*)d_in[3];
    const float* fc_w   = (const float*)d_in[4];
    const float* mlp_w  = (const float*)d_in[5];
    const float* n1_w   = (const float*)d_in[6];
    const float* n2_w   = (const float*)d_in[7];
    const float* lnf_w  = (const float*)d_in[8];
    const float* lm_w   = (const float*)d_in[9];
    float* out = (float*)d_out;
    (void)in_sizes; (void)n_in; (void)out_size;

    float *px, *pqkv, *ps;
    __half *pa_hi, *pa_lo, *ph_hi, *ph_lo;
    __half *pq_hi, *pq_lo, *pk_hi, *pk_lo, *pvt_hi, *pvt_lo, *pp_hi;
    __half *pwqkv, *pwattn, *pwfc, *pwmlp, *pwlm;
    cudaGetSymbolAddress((void**)&px,    g_x);
    cudaGetSymbolAddress((void**)&pqkv,  g_qkv);
    cudaGetSymbolAddress((void**)&ps,    g_s);
    cudaGetSymbolAddress((void**)&pa_hi, g_a_hi);
    cudaGetSymbolAddress((void**)&pa_lo, g_a_lo);
    cudaGetSymbolAddress((void**)&ph_hi, g_h_hi);
    cudaGetSymbolAddress((void**)&ph_lo, g_h_lo);
    cudaGetSymbolAddress((void**)&pq_hi, g_q_hi);
    cudaGetSymbolAddress((void**)&pq_lo, g_q_lo);
    cudaGetSymbolAddress((void**)&pk_hi, g_k_hi);
    cudaGetSymbolAddress((void**)&pk_lo, g_k_lo);
    cudaGetSymbolAddress((void**)&pvt_hi, g_vt_hi);
    cudaGetSymbolAddress((void**)&pvt_lo, g_vt_lo);
    cudaGetSymbolAddress((void**)&pp_hi, g_p_hi);
    cudaGetSymbolAddress((void**)&pwqkv, g_wqkv_h);
    cudaGetSymbolAddress((void**)&pwattn,g_wattn_h);
    cudaGetSymbolAddress((void**)&pwfc,  g_wfc_h);
    cudaGetSymbolAddress((void**)&pwmlp, g_wmlp_h);
    cudaGetSymbolAddress((void**)&pwlm,  g_wlm_h);

    cudaFuncSetAttribute(gemm_mma<0>, cudaFuncAttributeMaxDynamicSharedMemorySize, SM_TOTAL);
    cudaFuncSetAttribute(gemm_mma<1>, cudaFuncAttributeMaxDynamicSharedMemorySize, SM_TOTAL);
    cudaFuncSetAttribute(gemm_mma<2>, cudaFuncAttributeMaxDynamicSharedMemorySize, SM_TOTAL);
    cudaFuncSetAttribute(score_mma,   cudaFuncAttributeMaxDynamicSharedMemorySize, SM4_TOTAL);
    cudaFuncSetAttribute(av_mma,      cudaFuncAttributeMaxDynamicSharedMemorySize, SM3_TOTAL);

    // ---- one-time weight fp16 planes ----
    wconv_kernel<<<(int)(((size_t)NL*QKVD*Emb)/4/256), 256>>>(qkv_w,  pwqkv);
    wconv_kernel<<<(int)(((size_t)NL*Emb*(NH*HSZ))/4/256), 256>>>(attn_w, pwattn);
    wconv_kernel<<<(int)(((size_t)NL*FFD*Emb)/4/256), 256>>>(fc_w,   pwfc);
    wconv_kernel<<<(int)(((size_t)NL*Emb*FFD)/4/256), 256>>>(mlp_w,  pwmlp);
    wconv_kernel<<<(int)(((size_t)Voc*Emb)/4/256), 256>>>(lm_w,   pwlm);

    embed_kernel<<<NTOK*Emb/4/256, 256>>>(idx, wte);

    for (int l = 0; l < NL; l++) {
        rmsnorm_kernel<<<NTOK, 256>>>(px, n1_w + (size_t)l*Emb, pa_hi, pa_lo);
        gemm_mma<0><<<dim3(NTOK/128, QKVD/128), 256, SM_TOTAL>>>(
            pa_hi, pa_lo, pwqkv + (size_t)l*QKVD*Emb, pqkv, nullptr, nullptr, nullptr,
            NTOK, QKVD, Emb);
        rope_kernel<<<NTOK*(NH+NG)*64/256, 256>>>();
        vsplit_kernel<<<Bsz*NG*HSZ*Tseq/256, 256>>>();
        score_mma<<<dim3(Tseq/128, Tseq/128, Bsz*NH), 256, SM4_TOTAL>>>(
            pq_hi, pq_lo, pk_hi, pk_lo, ps);
        softmax_kernel<<<Bsz*NH*Tseq, 256>>>(ps, pp_hi);
        av_mma<<<dim3(1, Tseq/128, Bsz*NH), 256, SM3_TOTAL>>>(
            pp_hi, pvt_hi, pvt_lo, pa_hi, pa_lo);
        gemm_mma<2><<<dim3(NTOK/128, Emb/128), 256, SM_TOTAL>>>(
            pa_hi, pa_lo, pwattn + (size_t)l*Emb*(NH*HSZ), px, px, nullptr, nullptr,
            NTOK, Emb, NH*HSZ);
        rmsnorm_kernel<<<NTOK, 256>>>(px, n2_w + (size_t)l*Emb, pa_hi, pa_lo);
        gemm_mma<1><<<dim3(NTOK/128, FFD/128), 256, SM_TOTAL>>>(
            pa_hi, pa_lo, pwfc + (size_t)l*FFD*Emb, nullptr, nullptr, ph_hi, ph_lo,
            NTOK, FFD, Emb);
        gemm_mma<2><<<dim3(NTOK/128, Emb/128), 256, SM_TOTAL>>>(
            ph_hi, ph_lo, pwmlp + (size_t)l*Emb*FFD, px, px, nullptr, nullptr,
            NTOK, Emb, FFD);
    }

    rmsnorm_kernel<<<NTOK, 256>>>(px, lnf_w, pa_hi, pa_lo);
    gemm_mma<0><<<dim3(NTOK/128, Voc/128), 256, SM_TOTAL>>>(
        pa_hi, pa_lo, pwlm, out, nullptr, nullptr, nullptr, NTOK, Voc, Emb);
}

// round 14
// speedup vs baseline: 1.1678x; 1.0851x over previous
#include <cuda_runtime.h>
#include <cuda_fp16.h>
#include <math.h>
#include <stdint.h>

#define Bsz  2
#define Tseq 1024
#define Emb  2048
#define NH   16
#define NG   4
#define HSZ  128
#define NL   4
#define Voc  32000
#define FFD  8192
#define NTOK (Bsz*Tseq)                 // 2048
#define QKVD ((NH+2*NG)*HSZ)            // 3072
#define EPSF 1e-5f
#define ASCALE 0.08838834764831845f     // 1/sqrt(128)

// ---------------- scratch (device globals; no allocation allowed) ----------
__device__ __align__(128) float g_x  [NTOK*Emb];
__device__ __align__(128) float g_qkv[NTOK*QKVD];
__device__ __align__(128) float g_s  [(size_t)Bsz*NH*Tseq*Tseq];

// activation fp16 planes (hi/lo split)
__device__ __align__(128) __half g_a_hi[NTOK*Emb];
__device__ __align__(128) __half g_a_lo[NTOK*Emb];
__device__ __align__(128) __half g_h_hi[NTOK*FFD];
__device__ __align__(128) __half g_h_lo[NTOK*FFD];

// attention fp16 planes
__device__ __align__(128) __half g_q_hi[(size_t)Bsz*NH*Tseq*HSZ];
__device__ __align__(128) __half g_q_lo[(size_t)Bsz*NH*Tseq*HSZ];
__device__ __align__(128) __half g_k_hi[(size_t)Bsz*NG*Tseq*HSZ];
__device__ __align__(128) __half g_k_lo[(size_t)Bsz*NG*Tseq*HSZ];
__device__ __align__(128) __half g_vt_hi[(size_t)Bsz*NG*HSZ*Tseq];
__device__ __align__(128) __half g_vt_lo[(size_t)Bsz*NG*HSZ*Tseq];
__device__ __align__(128) __half g_p_hi[(size_t)Bsz*NH*Tseq*Tseq];

// weight fp16 planes (converted once per launch)
__device__ __align__(128) __half g_wqkv_h[(size_t)NL*QKVD*Emb];
__device__ __align__(128) __half g_wattn_h[(size_t)NL*Emb*(NH*HSZ)];
__device__ __align__(128) __half g_wfc_h [(size_t)NL*FFD*Emb];
__device__ __align__(128) __half g_wmlp_h[(size_t)NL*Emb*FFD];
__device__ __align__(128) __half g_wlm_h [(size_t)Voc*Emb];

// ==================== helpers ====================
__device__ __forceinline__ uint32_t smem_u32(const void* p) {
    uint32_t a;
    asm("{ .reg .u64 t; cvta.to.shared.u64 t, %1; cvt.u32.u64 %0, t; }" : "=r"(a) : "l"(p));
    return a;
}
__device__ __forceinline__ void ldsm_x4(uint32_t* r, uint32_t addr) {
    asm volatile("ldmatrix.sync.aligned.m8n8.x4.shared.b16 {%0,%1,%2,%3}, [%4];"
        : "=r"(r[0]), "=r"(r[1]), "=r"(r[2]), "=r"(r[3]) : "r"(addr));
}
__device__ __forceinline__ void ldsm_x2(uint32_t* r, uint32_t addr) {
    asm volatile("ldmatrix.sync.aligned.m8n8.x2.shared.b16 {%0,%1}, [%2];"
        : "=r"(r[0]), "=r"(r[1]) : "r"(addr));
}
__device__ __forceinline__ void mma_f16(float* d, const uint32_t* a, const uint32_t* b) {
    asm volatile(
        "mma.sync.aligned.m16n8k16.row.col.f32.f16.f16.f32 "
        "{%0,%1,%2,%3}, {%4,%5,%6,%7}, {%8,%9}, {%0,%1,%2,%3};"
        : "+f"(d[0]), "+f"(d[1]), "+f"(d[2]), "+f"(d[3])
        : "r"(a[0]), "r"(a[1]), "r"(a[2]), "r"(a[3]), "r"(b[0]), "r"(b[1]));
}
__device__ __forceinline__ void cp16(uint32_t saddr, const void* gptr) {
    asm volatile("cp.async.cg.shared.global [%0], [%1], 16;" :: "r"(saddr), "l"(gptr));
}
#define CP_COMMIT() asm volatile("cp.async.commit_group;" ::: "memory")
#define CP_WAIT(n)  asm volatile("cp.async.wait_group %0;" :: "n"(n) : "memory")

__device__ __forceinline__ float gelu_f(float x) {
    return 0.5f*x*(1.0f + tanhf(0.7978845608028654f*(x + 0.044715f*x*x*x)));
}
__device__ __forceinline__ void split4(float4 v, uint2& hh, uint2& ll) {
    __half h0 = __float2half_rn(v.x);
    __half h1 = __float2half_rn(v.y);
    __half h2 = __float2half_rn(v.z);
    __half h3 = __float2half_rn(v.w);
    __half l0 = __float2half_rn(v.x - __half2float(h0));
    __half l1 = __float2half_rn(v.y - __half2float(h1));
    __half l2 = __float2half_rn(v.z - __half2float(h2));
    __half l3 = __float2half_rn(v.w - __half2float(h3));
    hh.x = ((uint32_t)__half_as_ushort(h1) << 16) | __half_as_ushort(h0);
    hh.y = ((uint32_t)__half_as_ushort(h3) << 16) | __half_as_ushort(h2);
    ll.x = ((uint32_t)__half_as_ushort(l1) << 16) | __half_as_ushort(l0);
    ll.y = ((uint32_t)__half_as_ushort(l3) << 16) | __half_as_ushort(l2);
}
__device__ __forceinline__ void split2(float2 v, uint32_t& hh, uint32_t& ll) {
    __half h0 = __float2half_rn(v.x);
    __half h1 = __float2half_rn(v.y);
    __half l0 = __float2half_rn(v.x - __half2float(h0));
    __half l1 = __float2half_rn(v.y - __half2float(h1));
    hh = ((uint32_t)__half_as_ushort(h1) << 16) | __half_as_ushort(h0);
    ll = ((uint32_t)__half_as_ushort(l1) << 16) | __half_as_ushort(l0);
}

// ---------------- weight fp32 -> fp16 convert ----------------
__global__ void __launch_bounds__(256) wconv_kernel(const float* __restrict__ src,
                                                    __half* __restrict__ dst) {
    size_t i = (size_t)blockIdx.x * 256 + threadIdx.x;
    float4 v = ((const float4*)src)[i];
    uint2 hh;
    hh.x = ((uint32_t)__half_as_ushort(__float2half_rn(v.y)) << 16) | __half_as_ushort(__float2half_rn(v.x));
    hh.y = ((uint32_t)__half_as_ushort(__float2half_rn(v.w)) << 16) | __half_as_ushort(__float2half_rn(v.z));
    ((uint2*)dst)[i] = hh;
}

// ==================== cp.async 3-stage 2-pass fp16 GEMM (weights) ==========
// ROUND-10 CONFIG (proven): CTA 128x128, KC=32, 3 stages, 92KB -> 2 CTA/SM.
#define SROW 80
#define PLANE (128*SROW)        // 10240
#define SM_AHI 0
#define SM_ALO PLANE
#define SM_BHI (2*PLANE)
#define SM_STAGE (3*PLANE)      // 30720
#define NSTG 3
#define SM_TOTAL (NSTG*SM_STAGE) // 92160

template<int EPI>   // 0 plain fp32 C, 1 gelu -> half planes, 2 +Res -> fp32 C
__global__ void __launch_bounds__(256) gemm_mma(const __half* __restrict__ Ahi,
                                                const __half* __restrict__ Alo,
                                                const __half* __restrict__ Bh,
                                                float* __restrict__ C,
                                                const float* __restrict__ Res,
                                                __half* __restrict__ Chi,
                                                __half* __restrict__ Clo,
                                                int M, int N, int K) {
    extern __shared__ char sm[];
    const uint32_t smb = smem_u32(sm);
    const int tid  = threadIdx.x;
    const int lane = tid & 31;
    const int wid  = tid >> 5;
    const int wm   = wid & 3;
    const int wn   = wid >> 2;
    const int bm = blockIdx.x, bn = blockIdx.y;

    const char* Abase = (const char*)(Ahi + (size_t)bm*128*K);
    const char* Lbase = (const char*)(Alo + (size_t)bm*128*K);
    const char* Bbase = (const char*)(Bh  + (size_t)bn*128*K);
    const size_t Kb = (size_t)K * 2;

    const int c0 = tid, c1 = tid + 256;
    const int r0 = c0 >> 2, cb0 = (c0 & 3) * 16;
    const int r1 = c1 >> 2, cb1 = (c1 & 3) * 16;

    float acc[2][8][4];
#pragma unroll
    for (int i = 0; i < 2; i++)
#pragma unroll
        for (int j = 0; j < 8; j++)
#pragma unroll
            for (int q = 0; q < 4; q++) acc[i][j][q] = 0.f;

    const int NC = K >> 5;

    auto issue = [&](int st, int cc) {
        const uint32_t sb = smb + st * SM_STAGE;
        const size_t kb = (size_t)(cc << 6);
        cp16(sb + SM_AHI + r0*SROW + cb0, Abase + (size_t)r0*Kb + kb + cb0);
        cp16(sb + SM_AHI + r1*SROW + cb1, Abase + (size_t)r1*Kb + kb + cb1);
        cp16(sb + SM_ALO + r0*SROW + cb0, Lbase + (size_t)r0*Kb + kb + cb0);
        cp16(sb + SM_ALO + r1*SROW + cb1, Lbase + (size_t)r1*Kb + kb + cb1);
        cp16(sb + SM_BHI + r0*SROW + cb0, Bbase + (size_t)r0*Kb + kb + cb0);
        cp16(sb + SM_BHI + r1*SROW + cb1, Bbase + (size_t)r1*Kb + kb + cb1);
    };

    issue(0, 0); CP_COMMIT();
    issue(1, 1); CP_COMMIT();

    const int a_r  = wm*32 + (lane & 15);
    const int a_kb = (lane >> 4) << 4;
    const int b_r  = wn*64 + (lane & 7);
    const int b_kb = ((lane >> 3) & 1) << 4;

    int st = 0;
    for (int c = 0; c < NC; ++c) {
        if (c + 2 < NC) {
            int s2 = st + 2; if (s2 >= NSTG) s2 -= NSTG;
            issue(s2, c + 2);
            CP_COMMIT();
        }
        {
            int remaining = NC - 1 - c;
            if (remaining >= 2)      CP_WAIT(2);
            else if (remaining == 1) CP_WAIT(1);
            else                     CP_WAIT(0);
        }
        __syncthreads();

        const uint32_t sb = smb + st * SM_STAGE;
#pragma unroll
        for (int ks = 0; ks < 2; ks++) {
            uint32_t aHi[2][4], aLo[2][4];
#pragma unroll
            for (int mt = 0; mt < 2; mt++) {
                uint32_t base = sb + (a_r + mt*16)*SROW + ks*32 + a_kb;
                ldsm_x4(aHi[mt], base + SM_AHI);
                ldsm_x4(aLo[mt], base + SM_ALO);
            }
            uint32_t bHi[8][2];
#pragma unroll
            for (int nt = 0; nt < 8; nt++) {
                uint32_t base = sb + (b_r + nt*8)*SROW + ks*32 + b_kb;
                ldsm_x2(bHi[nt], base + SM_BHI);
            }
#pragma unroll
            for (int mt = 0; mt < 2; mt++)
#pragma unroll
                for (int nt = 0; nt < 8; nt++) {
                    mma_f16(acc[mt][nt], aHi[mt], bHi[nt]);
                    mma_f16(acc[mt][nt], aLo[mt], bHi[nt]);
                }
        }
        __syncthreads();
        if (++st == NSTG) st = 0;
    }

#pragma unroll
    for (int mt = 0; mt < 2; mt++) {
        int r0e = bm*128 + wm*32 + mt*16 + (lane >> 2);
#pragma unroll
        for (int nt = 0; nt < 8; nt++) {
            int col = bn*128 + wn*64 + nt*8 + (lane & 3)*2;
            float2 v0 = make_float2(acc[mt][nt][0], acc[mt][nt][1]);
            float2 v1 = make_float2(acc[mt][nt][2], acc[mt][nt][3]);
            if (EPI == 1) {
                v0.x = gelu_f(v0.x); v0.y = gelu_f(v0.y);
                v1.x = gelu_f(v1.x); v1.y = gelu_f(v1.y);
                size_t i0 = (size_t)r0e*N + col;
                size_t i1 = i0 + (size_t)8*N;
                uint32_t hh, ll;
                split2(v0, hh, ll);
                *(uint32_t*)(Chi + i0) = hh; *(uint32_t*)(Clo + i0) = ll;
                split2(v1, hh, ll);
                *(uint32_t*)(Chi + i1) = hh; *(uint32_t*)(Clo + i1) = ll;
            } else {
                float* p0 = C + (size_t)r0e*N + col;
                float* p1 = p0 + (size_t)8*N;
                if (EPI == 2) {
                    const float* q0 = Res + (size_t)r0e*N + col;
                    const float* q1 = q0 + (size_t)8*N;
                    float2 u0 = *(const float2*)q0;
                    float2 u1 = *(const float2*)q1;
                    v0.x += u0.x; v0.y += u0.y;
                    v1.x += u1.x; v1.y += u1.y;
                }
                *(float2*)p0 = v0;
                *(float2*)p1 = v1;
            }
        }
    }
}

// ==================== 1-pass fp16 GEMM for lm_head ====================
// A = fp16 (hi plane only), B = fp16. 2-plane stages, 61KB -> 2 CTA/SM.
#define SM1_A 0
#define SM1_B PLANE
#define SM1_STAGE (2*PLANE)        // 20480
#define SM1_TOTAL (3*SM1_STAGE)    // 61440

__global__ void __launch_bounds__(256) gemm_lm(const __half* __restrict__ Ah,
                                               const __half* __restrict__ Bh,
                                               float* __restrict__ C,
                                               int M, int N, int K) {
    extern __shared__ char sm[];
    const uint32_t smb = smem_u32(sm);
    const int tid  = threadIdx.x;
    const int lane = tid & 31;
    const int wid  = tid >> 5;
    const int wm   = wid & 3;
    const int wn   = wid >> 2;
    const int bm = blockIdx.x, bn = blockIdx.y;

    const char* Abase = (const char*)(Ah + (size_t)bm*128*K);
    const char* Bbase = (const char*)(Bh + (size_t)bn*128*K);
    const size_t Kb = (size_t)K * 2;

    const int c0 = tid, c1 = tid + 256;
    const int r0 = c0 >> 2, cb0 = (c0 & 3) * 16;
    const int r1 = c1 >> 2, cb1 = (c1 & 3) * 16;

    float acc[2][8][4];
#pragma unroll
    for (int i = 0; i < 2; i++)
#pragma unroll
        for (int j = 0; j < 8; j++)
#pragma unroll
            for (int q = 0; q < 4; q++) acc[i][j][q] = 0.f;

    const int NC = K >> 5;

    auto issue = [&](int st, int cc) {
        const uint32_t sb = smb + st * SM1_STAGE;
        const size_t kb = (size_t)(cc << 6);
        cp16(sb + SM1_A + r0*SROW + cb0, Abase + (size_t)r0*Kb + kb + cb0);
        cp16(sb + SM1_A + r1*SROW + cb1, Abase + (size_t)r1*Kb + kb + cb1);
        cp16(sb + SM1_B + r0*SROW + cb0, Bbase + (size_t)r0*Kb + kb + cb0);
        cp16(sb + SM1_B + r1*SROW + cb1, Bbase + (size_t)r1*Kb + kb + cb1);
    };

    issue(0, 0); CP_COMMIT();
    issue(1, 1); CP_COMMIT();

    const int a_r  = wm*32 + (lane & 15);
    const int a_kb = (lane >> 4) << 4;
    const int b_r  = wn*64 + (lane & 7);
    const int b_kb = ((lane >> 3) & 1) << 4;

    int st = 0;
    for (int c = 0; c < NC; ++c) {
        if (c + 2 < NC) {
            int s2 = st + 2; if (s2 >= 3) s2 -= 3;
            issue(s2, c + 2);
            CP_COMMIT();
        }
        {
            int remaining = NC - 1 - c;
            if (remaining >= 2)      CP_WAIT(2);
            else if (remaining == 1) CP_WAIT(1);
            else                     CP_WAIT(0);
        }
        __syncthreads();

        const uint32_t sb = smb + st * SM1_STAGE;
#pragma unroll
        for (int ks = 0; ks < 2; ks++) {
            uint32_t aF[2][4];
#pragma unroll
            for (int mt = 0; mt < 2; mt++)
                ldsm_x4(aF[mt], sb + SM1_A + (a_r + mt*16)*SROW + ks*32 + a_kb);
            uint32_t bF[8][2];
#pragma unroll
            for (int nt = 0; nt < 8; nt++)
                ldsm_x2(bF[nt], sb + SM1_B + (b_r + nt*8)*SROW + ks*32 + b_kb);
#pragma unroll
            for (int mt = 0; mt < 2; mt++)
#pragma unroll
                for (int nt = 0; nt < 8; nt++)
                    mma_f16(acc[mt][nt], aF[mt], bF[nt]);
        }
        __syncthreads();
        if (++st == 3) st = 0;
    }

#pragma unroll
    for (int mt = 0; mt < 2; mt++) {
        int r0e = bm*128 + wm*32 + mt*16 + (lane >> 2);
#pragma unroll
        for (int nt = 0; nt < 8; nt++) {
            int col = bn*128 + wn*64 + nt*8 + (lane & 3)*2;
            float* p0 = C + (size_t)r0e*N + col;
            float* p1 = p0 + (size_t)8*N;
            *(float2*)p0 = make_float2(acc[mt][nt][0], acc[mt][nt][1]);
            *(float2*)p1 = make_float2(acc[mt][nt][2], acc[mt][nt][3]);
        }
    }
}

// ==================== score MMA: 4-plane, 3-pass (Q,K hi/lo) ====================
#define SM4_AHI 0
#define SM4_ALO PLANE
#define SM4_BHI (2*PLANE)
#define SM4_BLO (3*PLANE)
#define SM4_STAGE (4*PLANE)        // 40960
#define SM4_TOTAL (3*SM4_STAGE)    // 122880

__global__ void __launch_bounds__(256) score_mma(const __half* __restrict__ Qhi,
                                                 const __half* __restrict__ Qlo,
                                                 const __half* __restrict__ Khi,
                                                 const __half* __restrict__ Klo,
                                                 float* __restrict__ Sout) {
    const int bn = blockIdx.x;
    const int bm = blockIdx.y;
    if (bn > bm) return;
    const int z = blockIdx.z;
    const int b = z >> 4, h = z & 15, g = h >> 2;

    extern __shared__ char sm[];
    const uint32_t smb = smem_u32(sm);
    const int tid  = threadIdx.x;
    const int lane = tid & 31;
    const int wid  = tid >> 5;
    const int wm   = wid & 3;
    const int wn   = wid >> 2;

    size_t aoff = ((size_t)(b*NH + h)*Tseq + (size_t)bm*128) * HSZ;
    size_t boff = ((size_t)(b*NG + g)*Tseq + (size_t)bn*128) * HSZ;
    const char* Abase = (const char*)(Qhi + aoff);
    const char* Lbase = (const char*)(Qlo + aoff);
    const char* Bbase = (const char*)(Khi + boff);
    const char* BLbase= (const char*)(Klo + boff);
    const size_t Kb = HSZ*2;
    const int NC = HSZ >> 5;    // 4

    const int c0 = tid, c1 = tid + 256;
    const int r0 = c0 >> 2, cb0 = (c0 & 3) * 16;
    const int r1 = c1 >> 2, cb1 = (c1 & 3) * 16;

    float acc[2][8][4];
#pragma unroll
    for (int i = 0; i < 2; i++)
#pragma unroll
        for (int j = 0; j < 8; j++)
#pragma unroll
            for (int q = 0; q < 4; q++) acc[i][j][q] = 0.f;

    auto issue = [&](int st, int cc) {
        const uint32_t sb = smb + st * SM4_STAGE;
        const size_t kb = (size_t)(cc << 6);
        cp16(sb + SM4_AHI + r0*SROW + cb0, Abase + (size_t)r0*Kb + kb + cb0);
        cp16(sb + SM4_AHI + r1*SROW + cb1, Abase + (size_t)r1*Kb + kb + cb1);
        cp16(sb + SM4_ALO + r0*SROW + cb0, Lbase + (size_t)r0*Kb + kb + cb0);
        cp16(sb + SM4_ALO + r1*SROW + cb1, Lbase + (size_t)r1*Kb + kb + cb1);
        cp16(sb + SM4_BHI + r0*SROW + cb0, Bbase + (size_t)r0*Kb + kb + cb0);
        cp16(sb + SM4_BHI + r1*SROW + cb1, Bbase + (size_t)r1*Kb + kb + cb1);
        cp16(sb + SM4_BLO + r0*SROW + cb0, BLbase + (size_t)r0*Kb + kb + cb0);
        cp16(sb + SM4_BLO + r1*SROW + cb1, BLbase + (size_t)r1*Kb + kb + cb1);
    };

    issue(0, 0); CP_COMMIT();
    issue(1, 1); CP_COMMIT();

    const int a_r  = wm*32 + (lane & 15);
    const int a_kb = (lane >> 4) << 4;
    const int b_r  = wn*64 + (lane & 7);
    const int b_kb = ((lane >> 3) & 1) << 4;

    int st = 0;
    for (int c = 0; c < NC; ++c) {
        if (c + 2 < NC) {
            int s2 = st + 2; if (s2 >= 3) s2 -= 3;
            issue(s2, c + 2);
            CP_COMMIT();
        }
        {
            int remaining = NC - 1 - c;
            if (remaining >= 2)      CP_WAIT(2);
            else if (remaining == 1) CP_WAIT(1);
            else                     CP_WAIT(0);
        }
        __syncthreads();

        const uint32_t sb = smb + st * SM4_STAGE;
#pragma unroll
        for (int ks = 0; ks < 2; ks++) {
            uint32_t aHi[2][4], aLo[2][4];
#pragma unroll
            for (int mt = 0; mt < 2; mt++) {
                uint32_t base = sb + (a_r + mt*16)*SROW + ks*32 + a_kb;
                ldsm_x4(aHi[mt], base + SM4_AHI);
                ldsm_x4(aLo[mt], base + SM4_ALO);
            }
#pragma unroll
            for (int nt = 0; nt < 8; nt++) {
                uint32_t bHi[2], bLo[2];
                uint32_t base = sb + (b_r + nt*8)*SROW + ks*32 + b_kb;
                ldsm_x2(bHi, base + SM4_BHI);
                ldsm_x2(bLo, base + SM4_BLO);
#pragma unroll
                for (int mt = 0; mt < 2; mt++) {
                    mma_f16(acc[mt][nt], aHi[mt], bHi);
                    mma_f16(acc[mt][nt], aHi[mt], bLo);
                    mma_f16(acc[mt][nt], aLo[mt], bHi);
                }
            }
        }
        __syncthreads();
        if (++st == 3) st = 0;
    }

#pragma unroll
    for (int mt = 0; mt < 2; mt++) {
        int rl = bm*128 + wm*32 + mt*16 + (lane >> 2);
#pragma unroll
        for (int nt = 0; nt < 8; nt++) {
            int col = wn*64 + nt*8 + (lane & 3)*2;
            float* p0 = Sout + (size_t)z*Tseq*Tseq + (size_t)rl*Tseq + bn*128 + col;
            float* p1 = p0 + (size_t)8*Tseq;
            *(float2*)p0 = make_float2(acc[mt][nt][0], acc[mt][nt][1]);
            *(float2*)p1 = make_float2(acc[mt][nt][2], acc[mt][nt][3]);
        }
    }
}

// ==================== AV MMA: 3-plane (P fp16; V hi/lo), 2-pass ====================
#define SM3_A   0
#define SM3_BHI PLANE
#define SM3_BLO (2*PLANE)
#define SM3_STAGE (3*PLANE)        // 30720
#define SM3_TOTAL (3*SM3_STAGE)    // 92160

__global__ void __launch_bounds__(256) av_mma(const __half* __restrict__ P,
                                              const __half* __restrict__ Vhi,
                                              const __half* __restrict__ Vlo,
                                              __half* __restrict__ Yhi,
                                              __half* __restrict__ Ylo) {
    const int bm = (int)(gridDim.y - 1 - blockIdx.y);    // long tiles first
    const int z = blockIdx.z;
    const int b = z >> 4, h = z & 15, g = h >> 2;

    extern __shared__ char sm[];
    const uint32_t smb = smem_u32(sm);
    const int tid  = threadIdx.x;
    const int lane = tid & 31;
    const int wid  = tid >> 5;
    const int wm   = wid & 3;
    const int wn   = wid >> 2;

    size_t aoff = (size_t)z*Tseq*Tseq + (size_t)bm*128*Tseq;
    size_t boff = (size_t)(b*NG + g)*HSZ*Tseq;
    const char* Abase = (const char*)(P + aoff);
    const char* Bbase = (const char*)(Vhi + boff);
    const char* BLbase= (const char*)(Vlo + boff);
    const size_t Kb = Tseq*2;
    const int NC = (bm + 1) << 2;          // 4..32

    const int c0 = tid, c1 = tid + 256;
    const int r0 = c0 >> 2, cb0 = (c0 & 3) * 16;
    const int r1 = c1 >> 2, cb1 = (c1 & 3) * 16;

    float acc[2][8][4];
#pragma unroll
    for (int i = 0; i < 2; i++)
#pragma unroll
        for (int j = 0; j < 8; j++)
#pragma unroll
            for (int q = 0; q < 4; q++) acc[i][j][q] = 0.f;

    auto issue = [&](int st, int cc) {
        const uint32_t sb = smb + st * SM3_STAGE;
        const size_t kb = (size_t)(cc << 6);
        cp16(sb + SM3_A   + r0*SROW + cb0, Abase + (size_t)r0*Kb + kb + cb0);
        cp16(sb + SM3_A   + r1*SROW + cb1, Abase + (size_t)r1*Kb + kb + cb1);
        cp16(sb + SM3_BHI + r0*SROW + cb0, Bbase + (size_t)r0*Kb + kb + cb0);
        cp16(sb + SM3_BHI + r1*SROW + cb1, Bbase + (size_t)r1*Kb + kb + cb1);
        cp16(sb + SM3_BLO + r0*SROW + cb0, BLbase + (size_t)r0*Kb + kb + cb0);
        cp16(sb + SM3_BLO + r1*SROW + cb1, BLbase + (size_t)r1*Kb + kb + cb1);
    };

    issue(0, 0); CP_COMMIT();
    issue(1, 1); CP_COMMIT();

    const int a_r  = wm*32 + (lane & 15);
    const int a_kb = (lane >> 4) << 4;
    const int b_r  = wn*64 + (lane & 7);
    const int b_kb = ((lane >> 3) & 1) << 4;

    int st = 0;
    for (int c = 0; c < NC; ++c) {
        if (c + 2 < NC) {
            int s2 = st + 2; if (s2 >= 3) s2 -= 3;
            issue(s2, c + 2);
            CP_COMMIT();
        }
        {
            int remaining = NC - 1 - c;
            if (remaining >= 2)      CP_WAIT(2);
            else if (remaining == 1) CP_WAIT(1);
            else                     CP_WAIT(0);
        }
        __syncthreads();

        const uint32_t sb = smb + st * SM3_STAGE;
#pragma unroll
        for (int ks = 0; ks < 2; ks++) {
            uint32_t aF[2][4];
#pragma unroll
            for (int mt = 0; mt < 2; mt++) {
                ldsm_x4(aF[mt], sb + SM3_A + (a_r + mt*16)*SROW + ks*32 + a_kb);
            }
#pragma unroll
            for (int nt = 0; nt < 8; nt++) {
                uint32_t bHi[2], bLo[2];
                uint32_t base = sb + (b_r + nt*8)*SROW + ks*32 + b_kb;
                ldsm_x2(bHi, base + SM3_BHI);
                ldsm_x2(bLo, base + SM3_BLO);
#pragma unroll
                for (int mt = 0; mt < 2; mt++) {
                    mma_f16(acc[mt][nt], aF[mt], bHi);
                    mma_f16(acc[mt][nt], aF[mt], bLo);
                }
            }
        }
        __syncthreads();
        if (++st == 3) st = 0;
    }

#pragma unroll
    for (int mt = 0; mt < 2; mt++) {
        int rl = bm*128 + wm*32 + mt*16 + (lane >> 2);
#pragma unroll
        for (int nt = 0; nt < 8; nt++) {
            int col = wn*64 + nt*8 + (lane & 3)*2;
            size_t i0 = ((size_t)b*Tseq + rl)*Emb + h*HSZ + col;
            size_t i1 = i0 + (size_t)8*Emb;
            uint32_t hh, ll;
            split2(make_float2(acc[mt][nt][0], acc[mt][nt][1]), hh, ll);
            *(uint32_t*)(Yhi + i0) = hh; *(uint32_t*)(Ylo + i0) = ll;
            split2(make_float2(acc[mt][nt][2], acc[mt][nt][3]), hh, ll);
            *(uint32_t*)(Yhi + i1) = hh; *(uint32_t*)(Ylo + i1) = ll;
        }
    }
}

// ---------------- embedding gather ----------------
__global__ void __launch_bounds__(256) embed_kernel(const int* __restrict__ idx,
                                                    const float* __restrict__ wte) {
    int i  = blockIdx.x * 256 + threadIdx.x;
    int bt = i >> 9;
    int e4 = i & 511;
    ((float4*)g_x)[i] = ((const float4*)wte)[(size_t)idx[bt]*512 + e4];
}

// ---------------- RMSNorm -> fp16 hi/lo planes ----------------
__global__ void __launch_bounds__(256) rmsnorm_kernel(const float* __restrict__ x,
                                                      const float* __restrict__ w,
                                                      __half* __restrict__ ohi,
                                                      __half* __restrict__ olo) {
    int row = blockIdx.x;
    int t = threadIdx.x;
    const float4* xr = (const float4*)(x + (size_t)row*Emb);
    float4 a = xr[t];
    float4 b = xr[t + 256];
    float ss = a.x*a.x + a.y*a.y + a.z*a.z + a.w*a.w
             + b.x*b.x + b.y*b.y + b.z*b.z + b.w*b.w;
#pragma unroll
    for (int o = 16; o; o >>= 1) ss += __shfl_xor_sync(0xffffffffu, ss, o);
    __shared__ float red[8];
    __shared__ float sinv;
    if ((t & 31) == 0) red[t >> 5] = ss;
    __syncthreads();
    if (t == 0) {
        float tot = red[0];
#pragma unroll
        for (int i = 1; i < 8; i++) tot += red[i];
        sinv = rsqrtf(tot * (1.0f/Emb) + EPSF);
    }
    __syncthreads();
    float inv = sinv;
    const float4* wr = (const float4*)w;
    float4 w0 = wr[t], w1 = wr[t+256];
    float4 va = make_float4(a.x*inv*w0.x, a.y*inv*w0.y, a.z*inv*w0.z, a.w*inv*w0.w);
    float4 vb = make_float4(b.x*inv*w1.x, b.y*inv*w1.y, b.z*inv*w1.z, b.w*inv*w1.w);
    uint2 hh, ll;
    uint2* hp = (uint2*)(ohi + (size_t)row*Emb);
    uint2* lp = (uint2*)(olo + (size_t)row*Emb);
    split4(va, hh, ll); hp[t]     = hh; lp[t]     = ll;
    split4(vb, hh, ll); hp[t+256] = hh; lp[t+256] = ll;
}

// ---------------- RoPE -> q/k fp16 hi/lo planes (head-major) --------------
__global__ void __launch_bounds__(256) rope_kernel() {
    int i    = blockIdx.x * 256 + threadIdx.x;
    int d    = i & 63;
    int rest = i >> 6;
    int head = rest % (NH + NG);
    int bt   = rest / (NH + NG);
    int b    = bt >> 10;
    int t    = bt & (Tseq - 1);
    size_t src = (size_t)bt*QKVD + (head < NH ? head*HSZ : NH*HSZ + (head-NH)*HSZ);
    float inv_freq = powf(10000.0f, -(float)d * (1.0f/64.0f));
    float ang = (float)t * inv_freq;
    float sn, cs;
    sincosf(ang, &sn, &cs);
    float x1 = g_qkv[src + d];
    float x2 = g_qkv[src + 64 + d];
    float r1 = x1*cs - x2*sn;
    float r2 = x2*cs + x1*sn;
    __half h1 = __float2half_rn(r1), h2 = __float2half_rn(r2);
    __half l1 = __float2half_rn(r1 - __half2float(h1));
    __half l2 = __float2half_rn(r2 - __half2float(h2));
    size_t dst;
    __half *phi, *plo;
    if (head < NH) {
        dst = ((size_t)(b*NH + head)*Tseq + t)*HSZ + d;
        phi = g_q_hi; plo = g_q_lo;
    } else {
        dst = ((size_t)(b*NG + (head - NH))*Tseq + t)*HSZ + d;
        phi = g_k_hi; plo = g_k_lo;
    }
    phi[dst] = h1;  phi[dst + 64] = h2;
    plo[dst] = l1;  plo[dst + 64] = l2;
}

// ---------------- V -> transposed fp16 hi/lo planes ----------------
__global__ void __launch_bounds__(256) vsplit_kernel() {
    int i = blockIdx.x * 256 + threadIdx.x;
    int t = i & (Tseq - 1);
    int rest = i >> 10;
    int d = rest & 127;
    rest >>= 7;
    int g = rest & 3;
    int b = rest >> 2;
    float v = g_qkv[((size_t)(b*Tseq + t))*QKVD + (NH+NG)*HSZ + g*HSZ + d];
    __half h = __float2half_rn(v);
    __half l = __float2half_rn(v - __half2float(h));
    size_t dst = ((size_t)(b*NG + g)*HSZ + d)*Tseq + t;
    g_vt_hi[dst] = h;
    g_vt_lo[dst] = l;
}

// ---------------- causal softmax -> P fp16 (rounded) ----------------
__global__ void __launch_bounds__(256) softmax_kernel(const float* __restrict__ S,
                                                      __half* __restrict__ Phi) {
    size_t z = blockIdx.x;
    int t = blockIdx.x & (Tseq - 1);
    int jlim4 = (((t >> 7) + 1) << 7) >> 2;
    const float4* row = (const float4*)(S + z*Tseq);
    int j4 = threadIdx.x;
    int j  = j4 << 2;
    bool act = j4 < jlim4;
    float4 v = make_float4(0.f, 0.f, 0.f, 0.f);
    if (act) v = row[j4];
    float s0 = (act && j   <= t) ? v.x*ASCALE : -1e30f;
    float s1 = (act && j+1 <= t) ? v.y*ASCALE : -1e30f;
    float s2 = (act && j+2 <= t) ? v.z*ASCALE : -1e30f;
    float s3 = (act && j+3 <= t) ? v.w*ASCALE : -1e30f;
    float m = fmaxf(fmaxf(s0, s1), fmaxf(s2, s3));
#pragma unroll
    for (int o = 16; o; o >>= 1) m = fmaxf(m, __shfl_xor_sync(0xffffffffu, m, o));
    __shared__ float red[8];
    __shared__ float bm2, bs;
    int tid = threadIdx.x;
    if ((tid & 31) == 0) red[tid >> 5] = m;
    __syncthreads();
    if (tid == 0) {
        float mm = red[0];
#pragma unroll
        for (int i = 1; i < 8; i++) mm = fmaxf(mm, red[i]);
        bm2 = mm;
    }
    __syncthreads();
    float mm = bm2;
    float p0 = (j   <= t) ? __expf(s0 - mm) : 0.f;
    float p1 = (j+1 <= t) ? __expf(s1 - mm) : 0.f;
    float p2 = (j+2 <= t) ? __expf(s2 - mm) : 0.f;
    float p3 = (j+3 <= t) ? __expf(s3 - mm) : 0.f;
    float sum = p0 + p1 + p2 + p3;
#pragma unroll
    for (int o = 16; o; o >>= 1) sum += __shfl_xor_sync(0xffffffffu, sum, o);
    __syncthreads();
    if ((tid & 31) == 0) red[tid >> 5] = sum;
    __syncthreads();
    if (tid == 0) {
        float tot = red[0];
#pragma unroll
        for (int i = 1; i < 8; i++) tot += red[i];
        bs = 1.0f / tot;
    }
    __syncthreads();
    float inv = bs;
    if (act) {
        uint2 hh;
        hh.x = ((uint32_t)__half_as_ushort(__float2half_rn(p1*inv)) << 16)
             |  __half_as_ushort(__float2half_rn(p0*inv));
        hh.y = ((uint32_t)__half_as_ushort(__float2half_rn(p3*inv)) << 16)
             |  __half_as_ushort(__float2half_rn(p2*inv));
        *(uint2*)(Phi + z*Tseq + j) = hh;
    }
}

// ---------------- host entry ----------------
extern "C" void kernel_launch(void* const* d_in, const int* in_sizes, int n_in,
                              void* d_out, int out_size) {
    const int*   idx    = (const int*)  d_in[0];
    const float* wte    = (const float*)d_in[1];
    const float* qkv_w  = (const float*)d_in[2];
    const float* attn_w = (const float*)d_in[3];
    const float* fc_w   = (const float*)d_in[4];
    const float* mlp_w  = (const float*)d_in[5];
    const float* n1_w   = (const float*)d_in[6];
    const float* n2_w   = (const float*)d_in[7];
    const float* lnf_w  = (const float*)d_in[8];
    const float* lm_w   = (const float*)d_in[9];
    float* out = (float*)d_out;
    (void)in_sizes; (void)n_in; (void)out_size;

    float *px, *pqkv, *ps;
    __half *pa_hi, *pa_lo, *ph_hi, *ph_lo;
    __half *pq_hi, *pq_lo, *pk_hi, *pk_lo, *pvt_hi, *pvt_lo, *pp_hi;
    __half *pwqkv, *pwattn, *pwfc, *pwmlp, *pwlm;
    cudaGetSymbolAddress((void**)&px,    g_x);
    cudaGetSymbolAddress((void**)&pqkv,  g_qkv);
    cudaGetSymbolAddress((void**)&ps,    g_s);
    cudaGetSymbolAddress((void**)&pa_hi, g_a_hi);
    cudaGetSymbolAddress((void**)&pa_lo, g_a_lo);
    cudaGetSymbolAddress((void**)&ph_hi, g_h_hi);
    cudaGetSymbolAddress((void**)&ph_lo, g_h_lo);
    cudaGetSymbolAddress((void**)&pq_hi, g_q_hi);
    cudaGetSymbolAddress((void**)&pq_lo, g_q_lo);
    cudaGetSymbolAddress((void**)&pk_hi, g_k_hi);
    cudaGetSymbolAddress((void**)&pk_lo, g_k_lo);
    cudaGetSymbolAddress((void**)&pvt_hi, g_vt_hi);
    cudaGetSymbolAddress((void**)&pvt_lo, g_vt_lo);
    cudaGetSymbolAddress((void**)&pp_hi, g_p_hi);
    cudaGetSymbolAddress((void**)&pwqkv, g_wqkv_h);
    cudaGetSymbolAddress((void**)&pwattn,g_wattn_h);
    cudaGetSymbolAddress((void**)&pwfc,  g_wfc_h);
    cudaGetSymbolAddress((void**)&pwmlp, g_wmlp_h);
    cudaGetSymbolAddress((void**)&pwlm,  g_wlm_h);

    cudaFuncSetAttribute(gemm_mma<0>, cudaFuncAttributeMaxDynamicSharedMemorySize, SM_TOTAL);
    cudaFuncSetAttribute(gemm_mma<1>, cudaFuncAttributeMaxDynamicSharedMemorySize, SM_TOTAL);
    cudaFuncSetAttribute(gemm_mma<2>, cudaFuncAttributeMaxDynamicSharedMemorySize, SM_TOTAL);
    cudaFuncSetAttribute(gemm_lm,     cudaFuncAttributeMaxDynamicSharedMemorySize, SM1_TOTAL);
    cudaFuncSetAttribute(score_mma,   cudaFuncAttributeMaxDynamicSharedMemorySize, SM4_TOTAL);
    cudaFuncSetAttribute(av_mma,      cudaFuncAttributeMaxDynamicSharedMemorySize, SM3_TOTAL);

    // ---- one-time weight fp16 planes ----
    wconv_kernel<<<(int)(((size_t)NL*QKVD*Emb)/4/256), 256>>>(qkv_w,  pwqkv);
    wconv_kernel<<<(int)(((size_t)NL*Emb*(NH*HSZ))/4/256), 256>>>(attn_w, pwattn);
    wconv_kernel<<<(int)(((size_t)NL*FFD*Emb)/4/256), 256>>>(fc_w,   pwfc);
    wconv_kernel<<<(int)(((size_t)NL*Emb*FFD)/4/256), 256>>>(mlp_w,  pwmlp);
    wconv_kernel<<<(int)(((size_t)Voc*Emb)/4/256), 256>>>(lm_w,   pwlm);

    embed_kernel<<<NTOK*Emb/4/256, 256>>>(idx, wte);

    for (int l = 0; l < NL; l++) {
        rmsnorm_kernel<<<NTOK, 256>>>(px, n1_w + (size_t)l*Emb, pa_hi, pa_lo);
        gemm_mma<0><<<dim3(NTOK/128, QKVD/128), 256, SM_TOTAL>>>(
            pa_hi, pa_lo, pwqkv + (size_t)l*QKVD*Emb, pqkv, nullptr, nullptr, nullptr,
            NTOK, QKVD, Emb);
        rope_kernel<<<NTOK*(NH+NG)*64/256, 256>>>();
        vsplit_kernel<<<Bsz*NG*HSZ*Tseq/256, 256>>>();
        score_mma<<<dim3(Tseq/128, Tseq/128, Bsz*NH), 256, SM4_TOTAL>>>(
            pq_hi, pq_lo, pk_hi, pk_lo, ps);
        softmax_kernel<<<Bsz*NH*Tseq, 256>>>(ps, pp_hi);
        av_mma<<<dim3(1, Tseq/128, Bsz*NH), 256, SM3_TOTAL>>>(
            pp_hi, pvt_hi, pvt_lo, pa_hi, pa_lo);
        gemm_mma<2><<<dim3(NTOK/128, Emb/128), 256, SM_TOTAL>>>(
            pa_hi, pa_lo, pwattn + (size_t)l*Emb*(NH*HSZ), px, px, nullptr, nullptr,
            NTOK, Emb, NH*HSZ);
        rmsnorm_kernel<<<NTOK, 256>>>(px, n2_w + (size_t)l*Emb, pa_hi, pa_lo);
        gemm_mma<1><<<dim3(NTOK/128, FFD/128), 256, SM_TOTAL>>>(
            pa_hi, pa_lo, pwfc + (size_t)l*FFD*Emb, nullptr, nullptr, ph_hi, ph_lo,
            NTOK, FFD, Emb);
        gemm_mma<2><<<dim3(NTOK/128, Emb/128), 256, SM_TOTAL>>>(
            ph_hi, ph_lo, pwmlp + (size_t)l*Emb*FFD, px, px, nullptr, nullptr,
            NTOK, Emb, FFD);
    }

    rmsnorm_kernel<<<NTOK, 256>>>(px, lnf_w, pa_hi, pa_lo);
    gemm_lm<<<dim3(NTOK/128, Voc/128), 256, SM1_TOTAL>>>(
        pa_hi, pwlm, out, NTOK, Voc, Emb);
}

// round 16
// speedup vs baseline: 1.5891x; 1.3608x over previous
#include <cuda_runtime.h>
#include <cuda_fp16.h>
#include <math.h>
#include <stdint.h>

#define Bsz  2
#define Tseq 1024
#define Emb  2048
#define NH   16
#define NG   4
#define HSZ  128
#define NL   4
#define Voc  32000
#define FFD  8192
#define NTOK (Bsz*Tseq)                 // 2048
#define QKVD ((NH+2*NG)*HSZ)            // 3072
#define EPSF 1e-5f
#define ASCALE 0.08838834764831845f     // 1/sqrt(128)

// ---------------- scratch (device globals; no allocation allowed) ----------
__device__ __align__(128) float g_x  [NTOK*Emb];
__device__ __align__(128) float g_qkv[NTOK*QKVD];
__device__ __align__(128) float g_s  [(size_t)Bsz*NH*Tseq*Tseq];

// activation fp16 planes
__device__ __align__(128) __half g_a_hi[NTOK*Emb];
__device__ __align__(128) __half g_h_hi[NTOK*FFD];

// attention fp16 planes
__device__ __align__(128) __half g_q_hi[(size_t)Bsz*NH*Tseq*HSZ];
__device__ __align__(128) __half g_q_lo[(size_t)Bsz*NH*Tseq*HSZ];
__device__ __align__(128) __half g_k_hi[(size_t)Bsz*NG*Tseq*HSZ];
__device__ __align__(128) __half g_k_lo[(size_t)Bsz*NG*Tseq*HSZ];
__device__ __align__(128) __half g_vt_hi[(size_t)Bsz*NG*HSZ*Tseq];
__device__ __align__(128) __half g_vt_lo[(size_t)Bsz*NG*HSZ*Tseq];
__device__ __align__(128) __half g_p_hi[(size_t)Bsz*NH*Tseq*Tseq];

// weight fp16 planes (converted once per launch)
__device__ __align__(128) __half g_wqkv_h[(size_t)NL*QKVD*Emb];
__device__ __align__(128) __half g_wattn_h[(size_t)NL*Emb*(NH*HSZ)];
__device__ __align__(128) __half g_wfc_h [(size_t)NL*FFD*Emb];
__device__ __align__(128) __half g_wmlp_h[(size_t)NL*Emb*FFD];
__device__ __align__(128) __half g_wlm_h [(size_t)Voc*Emb];

// ==================== helpers ====================
__device__ __forceinline__ uint32_t smem_u32(const void* p) {
    uint32_t a;
    asm("{ .reg .u64 t; cvta.to.shared.u64 t, %1; cvt.u32.u64 %0, t; }" : "=r"(a) : "l"(p));
    return a;
}
__device__ __forceinline__ void ldsm_x4(uint32_t* r, uint32_t addr) {
    asm volatile("ldmatrix.sync.aligned.m8n8.x4.shared.b16 {%0,%1,%2,%3}, [%4];"
        : "=r"(r[0]), "=r"(r[1]), "=r"(r[2]), "=r"(r[3]) : "r"(addr));
}
__device__ __forceinline__ void ldsm_x2(uint32_t* r, uint32_t addr) {
    asm volatile("ldmatrix.sync.aligned.m8n8.x2.shared.b16 {%0,%1}, [%2];"
        : "=r"(r[0]), "=r"(r[1]) : "r"(addr));
}
__device__ __forceinline__ void mma_f16(float* d, const uint32_t* a, const uint32_t* b) {
    asm volatile(
        "mma.sync.aligned.m16n8k16.row.col.f32.f16.f16.f32 "
        "{%0,%1,%2,%3}, {%4,%5,%6,%7}, {%8,%9}, {%0,%1,%2,%3};"
        : "+f"(d[0]), "+f"(d[1]), "+f"(d[2]), "+f"(d[3])
        : "r"(a[0]), "r"(a[1]), "r"(a[2]), "r"(a[3]), "r"(b[0]), "r"(b[1]));
}
__device__ __forceinline__ void cp16(uint32_t saddr, const void* gptr) {
    asm volatile("cp.async.cg.shared.global [%0], [%1], 16;" :: "r"(saddr), "l"(gptr));
}
#define CP_COMMIT() asm volatile("cp.async.commit_group;" ::: "memory")
#define CP_WAIT(n)  asm volatile("cp.async.wait_group %0;" :: "n"(n) : "memory")

__device__ __forceinline__ float gelu_f(float x) {
    return 0.5f*x*(1.0f + tanhf(0.7978845608028654f*(x + 0.044715f*x*x*x)));
}
__device__ __forceinline__ void split4(float4 v, uint2& hh, uint2& ll) {
    __half h0 = __float2half_rn(v.x);
    __half h1 = __float2half_rn(v.y);
    __half h2 = __float2half_rn(v.z);
    __half h3 = __float2half_rn(v.w);
    __half l0 = __float2half_rn(v.x - __half2float(h0));
    __half l1 = __float2half_rn(v.y - __half2float(h1));
    __half l2 = __float2half_rn(v.z - __half2float(h2));
    __half l3 = __float2half_rn(v.w - __half2float(h3));
    hh.x = ((uint32_t)__half_as_ushort(h1) << 16) | __half_as_ushort(h0);
    hh.y = ((uint32_t)__half_as_ushort(h3) << 16) | __half_as_ushort(h2);
    ll.x = ((uint32_t)__half_as_ushort(l1) << 16) | __half_as_ushort(l0);
    ll.y = ((uint32_t)__half_as_ushort(l3) << 16) | __half_as_ushort(l2);
}
__device__ __forceinline__ uint2 pack4(float4 v) {
    uint2 hh;
    hh.x = ((uint32_t)__half_as_ushort(__float2half_rn(v.y)) << 16) | __half_as_ushort(__float2half_rn(v.x));
    hh.y = ((uint32_t)__half_as_ushort(__float2half_rn(v.w)) << 16) | __half_as_ushort(__float2half_rn(v.z));
    return hh;
}
__device__ __forceinline__ uint32_t pack2(float2 v) {
    return ((uint32_t)__half_as_ushort(__float2half_rn(v.y)) << 16)
         |  __half_as_ushort(__float2half_rn(v.x));
}

// ---------------- weight fp32 -> fp16 convert ----------------
__global__ void __launch_bounds__(256) wconv_kernel(const float* __restrict__ src,
                                                    __half* __restrict__ dst) {
    size_t i = (size_t)blockIdx.x * 256 + threadIdx.x;
    float4 v = ((const float4*)src)[i];
    ((uint2*)dst)[i] = pack4(v);
}

// ==================== 1-pass fp16 GEMM, 4-stage cp.async ====================
// C[M,N] = A[M,K]*B[N,K]^T, A/B fp16 planes. CTA 128x128, KC=32.
// 2-plane stages (20KB), 4 stages = 80KB -> 2 CTA/SM.
#define SROW 80
#define PLANE (128*SROW)        // 10240
#define SM1_A 0
#define SM1_B PLANE
#define SM1_STAGE (2*PLANE)        // 20480
#define NSTG1 4
#define SM1_TOTAL (NSTG1*SM1_STAGE) // 81920

template<int EPI>   // 0 plain fp32 C, 1 gelu -> hi plane, 2 +Res -> fp32 C
__global__ void __launch_bounds__(256) gemm1(const __half* __restrict__ Ah,
                                             const __half* __restrict__ Bh,
                                             float* __restrict__ C,
                                             const float* __restrict__ Res,
                                             __half* __restrict__ Chi,
                                             int M, int N, int K) {
    extern __shared__ char sm[];
    const uint32_t smb = smem_u32(sm);
    const int tid  = threadIdx.x;
    const int lane = tid & 31;
    const int wid  = tid >> 5;
    const int wm   = wid & 3;
    const int wn   = wid >> 2;
    const int bm = blockIdx.x, bn = blockIdx.y;

    const char* Abase = (const char*)(Ah + (size_t)bm*128*K);
    const char* Bbase = (const char*)(Bh + (size_t)bn*128*K);
    const size_t Kb = (size_t)K * 2;

    const int c0 = tid, c1 = tid + 256;
    const int r0 = c0 >> 2, cb0 = (c0 & 3) * 16;
    const int r1 = c1 >> 2, cb1 = (c1 & 3) * 16;

    float acc[2][8][4];
#pragma unroll
    for (int i = 0; i < 2; i++)
#pragma unroll
        for (int j = 0; j < 8; j++)
#pragma unroll
            for (int q = 0; q < 4; q++) acc[i][j][q] = 0.f;

    const int NC = K >> 5;

    auto issue = [&](int st, int cc) {
        const uint32_t sb = smb + st * SM1_STAGE;
        const size_t kb = (size_t)(cc << 6);
        cp16(sb + SM1_A + r0*SROW + cb0, Abase + (size_t)r0*Kb + kb + cb0);
        cp16(sb + SM1_A + r1*SROW + cb1, Abase + (size_t)r1*Kb + kb + cb1);
        cp16(sb + SM1_B + r0*SROW + cb0, Bbase + (size_t)r0*Kb + kb + cb0);
        cp16(sb + SM1_B + r1*SROW + cb1, Bbase + (size_t)r1*Kb + kb + cb1);
    };

    issue(0, 0); CP_COMMIT();
    issue(1, 1); CP_COMMIT();
    issue(2, 2); CP_COMMIT();

    const int a_r  = wm*32 + (lane & 15);
    const int a_kb = (lane >> 4) << 4;
    const int b_r  = wn*64 + (lane & 7);
    const int b_kb = ((lane >> 3) & 1) << 4;

    int st = 0;
    for (int c = 0; c < NC; ++c) {
        if (c + 3 < NC) {
            int s3 = st + 3; if (s3 >= NSTG1) s3 -= NSTG1;
            issue(s3, c + 3);
            CP_COMMIT();
        }
        {
            int remaining = NC - 1 - c;
            if (remaining >= 3)      CP_WAIT(3);
            else if (remaining == 2) CP_WAIT(2);
            else if (remaining == 1) CP_WAIT(1);
            else                     CP_WAIT(0);
        }
        __syncthreads();

        const uint32_t sb = smb + st * SM1_STAGE;
#pragma unroll
        for (int ks = 0; ks < 2; ks++) {
            uint32_t aF[2][4];
#pragma unroll
            for (int mt = 0; mt < 2; mt++)
                ldsm_x4(aF[mt], sb + SM1_A + (a_r + mt*16)*SROW + ks*32 + a_kb);
            uint32_t bF[8][2];
#pragma unroll
            for (int nt = 0; nt < 8; nt++)
                ldsm_x2(bF[nt], sb + SM1_B + (b_r + nt*8)*SROW + ks*32 + b_kb);
#pragma unroll
            for (int mt = 0; mt < 2; mt++)
#pragma unroll
                for (int nt = 0; nt < 8; nt++)
                    mma_f16(acc[mt][nt], aF[mt], bF[nt]);
        }
        __syncthreads();
        if (++st == NSTG1) st = 0;
    }

#pragma unroll
    for (int mt = 0; mt < 2; mt++) {
        int r0e = bm*128 + wm*32 + mt*16 + (lane >> 2);
#pragma unroll
        for (int nt = 0; nt < 8; nt++) {
            int col = bn*128 + wn*64 + nt*8 + (lane & 3)*2;
            float2 v0 = make_float2(acc[mt][nt][0], acc[mt][nt][1]);
            float2 v1 = make_float2(acc[mt][nt][2], acc[mt][nt][3]);
            if (EPI == 1) {
                v0.x = gelu_f(v0.x); v0.y = gelu_f(v0.y);
                v1.x = gelu_f(v1.x); v1.y = gelu_f(v1.y);
                size_t i0 = (size_t)r0e*N + col;
                size_t i1 = i0 + (size_t)8*N;
                *(uint32_t*)(Chi + i0) = pack2(v0);
                *(uint32_t*)(Chi + i1) = pack2(v1);
            } else {
                float* p0 = C + (size_t)r0e*N + col;
                float* p1 = p0 + (size_t)8*N;
                if (EPI == 2) {
                    const float* q0 = Res + (size_t)r0e*N + col;
                    const float* q1 = q0 + (size_t)8*N;
                    float2 u0 = *(const float2*)q0;
                    float2 u1 = *(const float2*)q1;
                    v0.x += u0.x; v0.y += u0.y;
                    v1.x += u1.x; v1.y += u1.y;
                }
                *(float2*)p0 = v0;
                *(float2*)p1 = v1;
            }
        }
    }
}

// ==================== score MMA: 4-plane, 3-pass (Q,K hi/lo) ====================
#define SM4_AHI 0
#define SM4_ALO PLANE
#define SM4_BHI (2*PLANE)
#define SM4_BLO (3*PLANE)
#define SM4_STAGE (4*PLANE)        // 40960
#define SM4_TOTAL (3*SM4_STAGE)    // 122880

__global__ void __launch_bounds__(256) score_mma(const __half* __restrict__ Qhi,
                                                 const __half* __restrict__ Qlo,
                                                 const __half* __restrict__ Khi,
                                                 const __half* __restrict__ Klo,
                                                 float* __restrict__ Sout) {
    const int bn = blockIdx.x;
    const int bm = blockIdx.y;
    if (bn > bm) return;
    const int z = blockIdx.z;
    const int b = z >> 4, h = z & 15, g = h >> 2;

    extern __shared__ char sm[];
    const uint32_t smb = smem_u32(sm);
    const int tid  = threadIdx.x;
    const int lane = tid & 31;
    const int wid  = tid >> 5;
    const int wm   = wid & 3;
    const int wn   = wid >> 2;

    size_t aoff = ((size_t)(b*NH + h)*Tseq + (size_t)bm*128) * HSZ;
    size_t boff = ((size_t)(b*NG + g)*Tseq + (size_t)bn*128) * HSZ;
    const char* Abase = (const char*)(Qhi + aoff);
    const char* Lbase = (const char*)(Qlo + aoff);
    const char* Bbase = (const char*)(Khi + boff);
    const char* BLbase= (const char*)(Klo + boff);
    const size_t Kb = HSZ*2;
    const int NC = HSZ >> 5;    // 4

    const int c0 = tid, c1 = tid + 256;
    const int r0 = c0 >> 2, cb0 = (c0 & 3) * 16;
    const int r1 = c1 >> 2, cb1 = (c1 & 3) * 16;

    float acc[2][8][4];
#pragma unroll
    for (int i = 0; i < 2; i++)
#pragma unroll
        for (int j = 0; j < 8; j++)
#pragma unroll
            for (int q = 0; q < 4; q++) acc[i][j][q] = 0.f;

    auto issue = [&](int st, int cc) {
        const uint32_t sb = smb + st * SM4_STAGE;
        const size_t kb = (size_t)(cc << 6);
        cp16(sb + SM4_AHI + r0*SROW + cb0, Abase + (size_t)r0*Kb + kb + cb0);
        cp16(sb + SM4_AHI + r1*SROW + cb1, Abase + (size_t)r1*Kb + kb + cb1);
        cp16(sb + SM4_ALO + r0*SROW + cb0, Lbase + (size_t)r0*Kb + kb + cb0);
        cp16(sb + SM4_ALO + r1*SROW + cb1, Lbase + (size_t)r1*Kb + kb + cb1);
        cp16(sb + SM4_BHI + r0*SROW + cb0, Bbase + (size_t)r0*Kb + kb + cb0);
        cp16(sb + SM4_BHI + r1*SROW + cb1, Bbase + (size_t)r1*Kb + kb + cb1);
        cp16(sb + SM4_BLO + r0*SROW + cb0, BLbase + (size_t)r0*Kb + kb + cb0);
        cp16(sb + SM4_BLO + r1*SROW + cb1, BLbase + (size_t)r1*Kb + kb + cb1);
    };

    issue(0, 0); CP_COMMIT();
    issue(1, 1); CP_COMMIT();

    const int a_r  = wm*32 + (lane & 15);
    const int a_kb = (lane >> 4) << 4;
    const int b_r  = wn*64 + (lane & 7);
    const int b_kb = ((lane >> 3) & 1) << 4;

    int st = 0;
    for (int c = 0; c < NC; ++c) {
        if (c + 2 < NC) {
            int s2 = st + 2; if (s2 >= 3) s2 -= 3;
            issue(s2, c + 2);
            CP_COMMIT();
        }
        {
            int remaining = NC - 1 - c;
            if (remaining >= 2)      CP_WAIT(2);
            else if (remaining == 1) CP_WAIT(1);
            else                     CP_WAIT(0);
        }
        __syncthreads();

        const uint32_t sb = smb + st * SM4_STAGE;
#pragma unroll
        for (int ks = 0; ks < 2; ks++) {
            uint32_t aHi[2][4], aLo[2][4];
#pragma unroll
            for (int mt = 0; mt < 2; mt++) {
                uint32_t base = sb + (a_r + mt*16)*SROW + ks*32 + a_kb;
                ldsm_x4(aHi[mt], base + SM4_AHI);
                ldsm_x4(aLo[mt], base + SM4_ALO);
            }
#pragma unroll
            for (int nt = 0; nt < 8; nt++) {
                uint32_t bHi[2], bLo[2];
                uint32_t base = sb + (b_r + nt*8)*SROW + ks*32 + b_kb;
                ldsm_x2(bHi, base + SM4_BHI);
                ldsm_x2(bLo, base + SM4_BLO);
#pragma unroll
                for (int mt = 0; mt < 2; mt++) {
                    mma_f16(acc[mt][nt], aHi[mt], bHi);
                    mma_f16(acc[mt][nt], aHi[mt], bLo);
                    mma_f16(acc[mt][nt], aLo[mt], bHi);
                }
            }
        }
        __syncthreads();
        if (++st == 3) st = 0;
    }

#pragma unroll
    for (int mt = 0; mt < 2; mt++) {
        int rl = bm*128 + wm*32 + mt*16 + (lane >> 2);
#pragma unroll
        for (int nt = 0; nt < 8; nt++) {
            int col = wn*64 + nt*8 + (lane & 3)*2;
            float* p0 = Sout + (size_t)z*Tseq*Tseq + (size_t)rl*Tseq + bn*128 + col;
            float* p1 = p0 + (size_t)8*Tseq;
            *(float2*)p0 = make_float2(acc[mt][nt][0], acc[mt][nt][1]);
            *(float2*)p1 = make_float2(acc[mt][nt][2], acc[mt][nt][3]);
        }
    }
}

// ==================== AV MMA: 3-plane (P fp16; V hi/lo), 2-pass ====================
#define SM3_A   0
#define SM3_BHI PLANE
#define SM3_BLO (2*PLANE)
#define SM3_STAGE (3*PLANE)        // 30720
#define SM3_TOTAL (3*SM3_STAGE)    // 92160

__global__ void __launch_bounds__(256) av_mma(const __half* __restrict__ P,
                                              const __half* __restrict__ Vhi,
                                              const __half* __restrict__ Vlo,
                                              __half* __restrict__ Yhi) {
    const int bm = (int)(gridDim.y - 1 - blockIdx.y);    // long tiles first
    const int z = blockIdx.z;
    const int b = z >> 4, h = z & 15, g = h >> 2;

    extern __shared__ char sm[];
    const uint32_t smb = smem_u32(sm);
    const int tid  = threadIdx.x;
    const int lane = tid & 31;
    const int wid  = tid >> 5;
    const int wm   = wid & 3;
    const int wn   = wid >> 2;

    size_t aoff = (size_t)z*Tseq*Tseq + (size_t)bm*128*Tseq;
    size_t boff = (size_t)(b*NG + g)*HSZ*Tseq;
    const char* Abase = (const char*)(P + aoff);
    const char* Bbase = (const char*)(Vhi + boff);
    const char* BLbase= (const char*)(Vlo + boff);
    const size_t Kb = Tseq*2;
    const int NC = (bm + 1) << 2;          // 4..32

    const int c0 = tid, c1 = tid + 256;
    const int r0 = c0 >> 2, cb0 = (c0 & 3) * 16;
    const int r1 = c1 >> 2, cb1 = (c1 & 3) * 16;

    float acc[2][8][4];
#pragma unroll
    for (int i = 0; i < 2; i++)
#pragma unroll
        for (int j = 0; j < 8; j++)
#pragma unroll
            for (int q = 0; q < 4; q++) acc[i][j][q] = 0.f;

    auto issue = [&](int st, int cc) {
        const uint32_t sb = smb + st * SM3_STAGE;
        const size_t kb = (size_t)(cc << 6);
        cp16(sb + SM3_A   + r0*SROW + cb0, Abase + (size_t)r0*Kb + kb + cb0);
        cp16(sb + SM3_A   + r1*SROW + cb1, Abase + (size_t)r1*Kb + kb + cb1);
        cp16(sb + SM3_BHI + r0*SROW + cb0, Bbase + (size_t)r0*Kb + kb + cb0);
        cp16(sb + SM3_BHI + r1*SROW + cb1, Bbase + (size_t)r1*Kb + kb + cb1);
        cp16(sb + SM3_BLO + r0*SROW + cb0, BLbase + (size_t)r0*Kb + kb + cb0);
        cp16(sb + SM3_BLO + r1*SROW + cb1, BLbase + (size_t)r1*Kb + kb + cb1);
    };

    issue(0, 0); CP_COMMIT();
    issue(1, 1); CP_COMMIT();

    const int a_r  = wm*32 + (lane & 15);
    const int a_kb = (lane >> 4) << 4;
    const int b_r  = wn*64 + (lane & 7);
    const int b_kb = ((lane >> 3) & 1) << 4;

    int st = 0;
    for (int c = 0; c < NC; ++c) {
        if (c + 2 < NC) {
            int s2 = st + 2; if (s2 >= 3) s2 -= 3;
            issue(s2, c + 2);
            CP_COMMIT();
        }
        {
            int remaining = NC - 1 - c;
            if (remaining >= 2)      CP_WAIT(2);
            else if (remaining == 1) CP_WAIT(1);
            else                     CP_WAIT(0);
        }
        __syncthreads();

        const uint32_t sb = smb + st * SM3_STAGE;
#pragma unroll
        for (int ks = 0; ks < 2; ks++) {
            uint32_t aF[2][4];
#pragma unroll
            for (int mt = 0; mt < 2; mt++) {
                ldsm_x4(aF[mt], sb + SM3_A + (a_r + mt*16)*SROW + ks*32 + a_kb);
            }
#pragma unroll
            for (int nt = 0; nt < 8; nt++) {
                uint32_t bHi[2], bLo[2];
                uint32_t base = sb + (b_r + nt*8)*SROW + ks*32 + b_kb;
                ldsm_x2(bHi, base + SM3_BHI);
                ldsm_x2(bLo, base + SM3_BLO);
#pragma unroll
                for (int mt = 0; mt < 2; mt++) {
                    mma_f16(acc[mt][nt], aF[mt], bHi);
                    mma_f16(acc[mt][nt], aF[mt], bLo);
                }
            }
        }
        __syncthreads();
        if (++st == 3) st = 0;
    }

#pragma unroll
    for (int mt = 0; mt < 2; mt++) {
        int rl = bm*128 + wm*32 + mt*16 + (lane >> 2);
#pragma unroll
        for (int nt = 0; nt < 8; nt++) {
            int col = wn*64 + nt*8 + (lane & 3)*2;
            size_t i0 = ((size_t)b*Tseq + rl)*Emb + h*HSZ + col;
            size_t i1 = i0 + (size_t)8*Emb;
            *(uint32_t*)(Yhi + i0) = pack2(make_float2(acc[mt][nt][0], acc[mt][nt][1]));
            *(uint32_t*)(Yhi + i1) = pack2(make_float2(acc[mt][nt][2], acc[mt][nt][3]));
        }
    }
}

// ---------------- embedding gather ----------------
__global__ void __launch_bounds__(256) embed_kernel(const int* __restrict__ idx,
                                                    const float* __restrict__ wte) {
    int i  = blockIdx.x * 256 + threadIdx.x;
    int bt = i >> 9;
    int e4 = i & 511;
    ((float4*)g_x)[i] = ((const float4*)wte)[(size_t)idx[bt]*512 + e4];
}

// ---------------- RMSNorm -> fp16 hi plane ----------------
__global__ void __launch_bounds__(256) rmsnorm_kernel(const float* __restrict__ x,
                                                      const float* __restrict__ w,
                                                      __half* __restrict__ ohi) {
    int row = blockIdx.x;
    int t = threadIdx.x;
    const float4* xr = (const float4*)(x + (size_t)row*Emb);
    float4 a = xr[t];
    float4 b = xr[t + 256];
    float ss = a.x*a.x + a.y*a.y + a.z*a.z + a.w*a.w
             + b.x*b.x + b.y*b.y + b.z*b.z + b.w*b.w;
#pragma unroll
    for (int o = 16; o; o >>= 1) ss += __shfl_xor_sync(0xffffffffu, ss, o);
    __shared__ float red[8];
    __shared__ float sinv;
    if ((t & 31) == 0) red[t >> 5] = ss;
    __syncthreads();
    if (t == 0) {
        float tot = red[0];
#pragma unroll
        for (int i = 1; i < 8; i++) tot += red[i];
        sinv = rsqrtf(tot * (1.0f/Emb) + EPSF);
    }
    __syncthreads();
    float inv = sinv;
    const float4* wr = (const float4*)w;
    float4 w0 = wr[t], w1 = wr[t+256];
    float4 va = make_float4(a.x*inv*w0.x, a.y*inv*w0.y, a.z*inv*w0.z, a.w*inv*w0.w);
    float4 vb = make_float4(b.x*inv*w1.x, b.y*inv*w1.y, b.z*inv*w1.z, b.w*inv*w1.w);
    uint2* hp = (uint2*)(ohi + (size_t)row*Emb);
    hp[t]     = pack4(va);
    hp[t+256] = pack4(vb);
}

// ---------------- RoPE -> q/k fp16 hi/lo planes (head-major) --------------
__global__ void __launch_bounds__(256) rope_kernel() {
    int i    = blockIdx.x * 256 + threadIdx.x;
    int d    = i & 63;
    int rest = i >> 6;
    int head = rest % (NH + NG);
    int bt   = rest / (NH + NG);
    int b    = bt >> 10;
    int t    = bt & (Tseq - 1);
    size_t src = (size_t)bt*QKVD + (head < NH ? head*HSZ : NH*HSZ + (head-NH)*HSZ);
    float inv_freq = powf(10000.0f, -(float)d * (1.0f/64.0f));
    float ang = (float)t * inv_freq;
    float sn, cs;
    sincosf(ang, &sn, &cs);
    float x1 = g_qkv[src + d];
    float x2 = g_qkv[src + 64 + d];
    float r1 = x1*cs - x2*sn;
    float r2 = x2*cs + x1*sn;
    __half h1 = __float2half_rn(r1), h2 = __float2half_rn(r2);
    __half l1 = __float2half_rn(r1 - __half2float(h1));
    __half l2 = __float2half_rn(r2 - __half2float(h2));
    size_t dst;
    __half *phi, *plo;
    if (head < NH) {
        dst = ((size_t)(b*NH + head)*Tseq + t)*HSZ + d;
        phi = g_q_hi; plo = g_q_lo;
    } else {
        dst = ((size_t)(b*NG + (head - NH))*Tseq + t)*HSZ + d;
        phi = g_k_hi; plo = g_k_lo;
    }
    phi[dst] = h1;  phi[dst + 64] = h2;
    plo[dst] = l1;  plo[dst + 64] = l2;
}

// ---------------- V -> transposed fp16 hi/lo planes ----------------
__global__ void __launch_bounds__(256) vsplit_kernel() {
    int i = blockIdx.x * 256 + threadIdx.x;
    int t = i & (Tseq - 1);
    int rest = i >> 10;
    int d = rest & 127;
    rest >>= 7;
    int g = rest & 3;
    int b = rest >> 2;
    float v = g_qkv[((size_t)(b*Tseq + t))*QKVD + (NH+NG)*HSZ + g*HSZ + d];
    __half h = __float2half_rn(v);
    __half l = __float2half_rn(v - __half2float(h));
    size_t dst = ((size_t)(b*NG + g)*HSZ + d)*Tseq + t;
    g_vt_hi[dst] = h;
    g_vt_lo[dst] = l;
}

// ---------------- causal softmax -> P fp16 (rounded) ----------------
__global__ void __launch_bounds__(256) softmax_kernel(const float* __restrict__ S,
                                                      __half* __restrict__ Phi) {
    size_t z = blockIdx.x;
    int t = blockIdx.x & (Tseq - 1);
    int jlim4 = (((t >> 7) + 1) << 7) >> 2;
    const float4* row = (const float4*)(S + z*Tseq);
    int j4 = threadIdx.x;
    int j  = j4 << 2;
    bool act = j4 < jlim4;
    float4 v = make_float4(0.f, 0.f, 0.f, 0.f);
    if (act) v = row[j4];
    float s0 = (act && j   <= t) ? v.x*ASCALE : -1e30f;
    float s1 = (act && j+1 <= t) ? v.y*ASCALE : -1e30f;
    float s2 = (act && j+2 <= t) ? v.z*ASCALE : -1e30f;
    float s3 = (act && j+3 <= t) ? v.w*ASCALE : -1e30f;
    float m = fmaxf(fmaxf(s0, s1), fmaxf(s2, s3));
#pragma unroll
    for (int o = 16; o; o >>= 1) m = fmaxf(m, __shfl_xor_sync(0xffffffffu, m, o));
    __shared__ float red[8];
    __shared__ float bm2, bs;
    int tid = threadIdx.x;
    if ((tid & 31) == 0) red[tid >> 5] = m;
    __syncthreads();
    if (tid == 0) {
        float mm = red[0];
#pragma unroll
        for (int i = 1; i < 8; i++) mm = fmaxf(mm, red[i]);
        bm2 = mm;
    }
    __syncthreads();
    float mm = bm2;
    float p0 = (j   <= t) ? __expf(s0 - mm) : 0.f;
    float p1 = (j+1 <= t) ? __expf(s1 - mm) : 0.f;
    float p2 = (j+2 <= t) ? __expf(s2 - mm) : 0.f;
    float p3 = (j+3 <= t) ? __expf(s3 - mm) : 0.f;
    float sum = p0 + p1 + p2 + p3;
#pragma unroll
    for (int o = 16; o; o >>= 1) sum += __shfl_xor_sync(0xffffffffu, sum, o);
    __syncthreads();
    if ((tid & 31) == 0) red[tid >> 5] = sum;
    __syncthreads();
    if (tid == 0) {
        float tot = red[0];
#pragma unroll
        for (int i = 1; i < 8; i++) tot += red[i];
        bs = 1.0f / tot;
    }
    __syncthreads();
    float inv = bs;
    if (act) {
        *(uint2*)(Phi + z*Tseq + j) =
            pack4(make_float4(p0*inv, p1*inv, p2*inv, p3*inv));
    }
}

// ---------------- host entry ----------------
extern "C" void kernel_launch(void* const* d_in, const int* in_sizes, int n_in,
                              void* d_out, int out_size) {
    const int*   idx    = (const int*)  d_in[0];
    const float* wte    = (const float*)d_in[1];
    const float* qkv_w  = (const float*)d_in[2];
    const float* attn_w = (const float*)d_in[3];
    const float* fc_w   = (const float*)d_in[4];
    const float* mlp_w  = (const float*)d_in[5];
    const float* n1_w   = (const float*)d_in[6];
    const float* n2_w   = (const float*)d_in[7];
    const float* lnf_w  = (const float*)d_in[8];
    const float* lm_w   = (const float*)d_in[9];
    float* out = (float*)d_out;
    (void)in_sizes; (void)n_in; (void)out_size;

    float *px, *pqkv, *ps;
    __half *pa_hi, *ph_hi;
    __half *pq_hi, *pq_lo, *pk_hi, *pk_lo, *pvt_hi, *pvt_lo, *pp_hi;
    __half *pwqkv, *pwattn, *pwfc, *pwmlp, *pwlm;
    cudaGetSymbolAddress((void**)&px,    g_x);
    cudaGetSymbolAddress((void**)&pqkv,  g_qkv);
    cudaGetSymbolAddress((void**)&ps,    g_s);
    cudaGetSymbolAddress((void**)&pa_hi, g_a_hi);
    cudaGetSymbolAddress((void**)&ph_hi, g_h_hi);
    cudaGetSymbolAddress((void**)&pq_hi, g_q_hi);
    cudaGetSymbolAddress((void**)&pq_lo, g_q_lo);
    cudaGetSymbolAddress((void**)&pk_hi, g_k_hi);
    cudaGetSymbolAddress((void**)&pk_lo, g_k_lo);
    cudaGetSymbolAddress((void**)&pvt_hi, g_vt_hi);
    cudaGetSymbolAddress((void**)&pvt_lo, g_vt_lo);
    cudaGetSymbolAddress((void**)&pp_hi, g_p_hi);
    cudaGetSymbolAddress((void**)&pwqkv, g_wqkv_h);
    cudaGetSymbolAddress((void**)&pwattn,g_wattn_h);
    cudaGetSymbolAddress((void**)&pwfc,  g_wfc_h);
    cudaGetSymbolAddress((void**)&pwmlp, g_wmlp_h);
    cudaGetSymbolAddress((void**)&pwlm,  g_wlm_h);

    cudaFuncSetAttribute(gemm1<0>, cudaFuncAttributeMaxDynamicSharedMemorySize, SM1_TOTAL);
    cudaFuncSetAttribute(gemm1<1>, cudaFuncAttributeMaxDynamicSharedMemorySize, SM1_TOTAL);
    cudaFuncSetAttribute(gemm1<2>, cudaFuncAttributeMaxDynamicSharedMemorySize, SM1_TOTAL);
    cudaFuncSetAttribute(score_mma, cudaFuncAttributeMaxDynamicSharedMemorySize, SM4_TOTAL);
    cudaFuncSetAttribute(av_mma,    cudaFuncAttributeMaxDynamicSharedMemorySize, SM3_TOTAL);

    // ---- one-time weight fp16 planes ----
    wconv_kernel<<<(int)(((size_t)NL*QKVD*Emb)/4/256), 256>>>(qkv_w,  pwqkv);
    wconv_kernel<<<(int)(((size_t)NL*Emb*(NH*HSZ))/4/256), 256>>>(attn_w, pwattn);
    wconv_kernel<<<(int)(((size_t)NL*FFD*Emb)/4/256), 256>>>(fc_w,   pwfc);
    wconv_kernel<<<(int)(((size_t)NL*Emb*FFD)/4/256), 256>>>(mlp_w,  pwmlp);
    wconv_kernel<<<(int)(((size_t)Voc*Emb)/4/256), 256>>>(lm_w,   pwlm);

    embed_kernel<<<NTOK*Emb/4/256, 256>>>(idx, wte);

    for (int l = 0; l < NL; l++) {
        rmsnorm_kernel<<<NTOK, 256>>>(px, n1_w + (size_t)l*Emb, pa_hi);
        gemm1<0><<<dim3(NTOK/128, QKVD/128), 256, SM1_TOTAL>>>(
            pa_hi, pwqkv + (size_t)l*QKVD*Emb, pqkv, nullptr, nullptr,
            NTOK, QKVD, Emb);
        rope_kernel<<<NTOK*(NH+NG)*64/256, 256>>>();
        vsplit_kernel<<<Bsz*NG*HSZ*Tseq/256, 256>>>();
        score_mma<<<dim3(Tseq/128, Tseq/128, Bsz*NH), 256, SM4_TOTAL>>>(
            pq_hi, pq_lo, pk_hi, pk_lo, ps);
        softmax_kernel<<<Bsz*NH*Tseq, 256>>>(ps, pp_hi);
        av_mma<<<dim3(1, Tseq/128, Bsz*NH), 256, SM3_TOTAL>>>(
            pp_hi, pvt_hi, pvt_lo, pa_hi);
        gemm1<2><<<dim3(NTOK/128, Emb/128), 256, SM1_TOTAL>>>(
            pa_hi, pwattn + (size_t)l*Emb*(NH*HSZ), px, px, nullptr,
            NTOK, Emb, NH*HSZ);
        rmsnorm_kernel<<<NTOK, 256>>>(px, n2_w + (size_t)l*Emb, pa_hi);
        gemm1<1><<<dim3(NTOK/128, FFD/128), 256, SM1_TOTAL>>>(
            pa_hi, pwfc + (size_t)l*FFD*Emb, nullptr, nullptr, ph_hi,
            NTOK, FFD, Emb);
        gemm1<2><<<dim3(NTOK/128, Emb/128), 256, SM1_TOTAL>>>(
            ph_hi, pwmlp + (size_t)l*Emb*FFD, px, px, nullptr,
            NTOK, Emb, FFD);
    }

    rmsnorm_kernel<<<NTOK, 256>>>(px, lnf_w, pa_hi);
    gemm1<0><<<dim3(NTOK/128, Voc/128), 256, SM1_TOTAL>>>(
        pa_hi, pwlm, out, nullptr, nullptr, NTOK, Voc, Emb);
}